// round 12
// baseline (speedup 1.0000x reference)
#include <cuda_runtime.h>
#include <cuda_bf16.h>
#include <mma.h>
#include <math.h>
#include <float.h>

using namespace nvcuda;

#define NEG_BIG (-3.402823466e38f)

constexpr int Bb = 2, TQn = 1024, TKn = 2048, DQn = 1024, DCn = 768, Hn = 16, DHn = 64;

// Scratch (allocation-free rule: __device__ globals), referenced only in device code.
__device__ float g_Q[Bb * Hn * TQn * DHn];          // (b,h,q,d)   8 MB
__device__ float g_K[Bb * Hn * TKn * DHn];          // (b,h,k,d)  16 MB
__device__ float g_V[Bb * Hn * TKn * DHn];          // (b,h,k,d)  16 MB
__device__ float g_L[(size_t)Bb * Hn * TQn * TKn];  // logits 256 MB
__device__ int   g_mask_mode;
// bf16x2 split planes (V / out projections only — selection-independent)
__device__ __nv_bfloat16 g_Asp[2ull * 4096 * 1024];     // activation splits
__device__ __nv_bfloat16 g_Ws[2][2ull * 1024 * 1024];   // transposed weight splits [n][k]: 0=Wv, 1=Wo

// ---------------- packed f32x2 helpers ----------------
__device__ __forceinline__ unsigned long long pack2(float x) {
    unsigned long long r; asm("mov.b64 %0, {%1, %1};" : "=l"(r) : "f"(x)); return r;
}
#define FFMA2(acc, a, b) asm("fma.rn.f32x2 %0, %1, %2, %0;" : "+l"(acc) : "l"(a), "l"(b))
__device__ __forceinline__ void unpack2(unsigned long long v, float& lo, float& hi) {
    asm("mov.b64 {%0, %1}, %2;" : "=f"(lo), "=f"(hi) : "l"(v));
}

// ---------------------------------------------------------------------------
// Mask dtype detection
// ---------------------------------------------------------------------------
__global__ void detect_mask_kernel(const unsigned char* __restrict__ m)
{
    __shared__ int s_big, s_mis;
    if (threadIdx.x == 0) { s_big = 0; s_mis = 0; }
    __syncthreads();
    int big = 0, mis = 0;
    for (int i = threadIdx.x; i < Bb * TKn; i += 256) {
        unsigned char v = m[i];
        if (v > 1) big = 1;
        else if (v == 1 && (i & 3)) mis = 1;
    }
    if (big) atomicOr(&s_big, 1);
    if (mis) atomicOr(&s_mis, 1);
    __syncthreads();
    if (threadIdx.x == 0) g_mask_mode = s_big ? 2 : (s_mis ? 0 : 1);
}

__device__ __forceinline__ unsigned char mask_at(const void* mask, int mode, int idx)
{
    if (mode == 2) return ((const float*)mask)[idx] != 0.f;
    if (mode == 1) return ((const int*)mask)[idx] != 0;
    return ((const unsigned char*)mask)[idx];
}

// ---------------------------------------------------------------------------
// Batched Q+K projection GEMM in ONE launch (wave-packing fix).
// CTA id < 128: Q tile (x @ Wq + bq -> g_Q head layout, K=1024, T=TQn)
// CTA id >= 128: K tile (ctx @ Wk + bk -> g_K head layout, K=768, T=TKn)
// Inner loop code identical to the round-6 proven gemm_k (bitwise chains).
// ---------------------------------------------------------------------------
__global__ __launch_bounds__(256, 2) void qkproj_k(
    const float* __restrict__ x,   const float* __restrict__ Wq, const float* __restrict__ bq,
    const float* __restrict__ ctx, const float* __restrict__ Wk, const float* __restrict__ bk)
{
    __shared__ float As[2][8][128];
    __shared__ float Bs[2][8][132];
    const int tid = threadIdx.x;
    const int tx = tid & 15, ty = tid >> 4;

    int cid = blockIdx.x;
    const float *A, *W, *bias;
    float* C;
    int K, T, m0, n0;
    if (cid < 128) {
        A = x; W = Wq; bias = bq; C = g_Q; K = 1024; T = TQn;
        m0 = (cid >> 3) * 128; n0 = (cid & 7) * 128;
    } else {
        cid -= 128;
        A = ctx; W = Wk; bias = bk; C = g_K; K = 768; T = TKn;
        m0 = (cid >> 3) * 128; n0 = (cid & 7) * 128;
    }
    const int N = 1024;

    unsigned long long acc2[8][4];
#pragma unroll
    for (int i = 0; i < 8; ++i)
#pragma unroll
        for (int jp = 0; jp < 4; ++jp) acc2[i][jp] = 0ull;

    const int arow = tid >> 1, acol = (tid & 1) * 4;
    const int brow = tid >> 5, bcol = (tid & 31) * 4;
    const float* Ap = A + (size_t)(m0 + arow) * K + acol;
    const float* Wp = W + (size_t)brow * N + n0 + bcol;

    {
        float4 av = *(const float4*)(Ap);
        float4 bv = *(const float4*)(Wp);
        As[0][acol + 0][arow] = av.x;
        As[0][acol + 1][arow] = av.y;
        As[0][acol + 2][arow] = av.z;
        As[0][acol + 3][arow] = av.w;
        *(float4*)&Bs[0][brow][bcol] = bv;
    }
    __syncthreads();

    int buf = 0;
    for (int k0 = 0; k0 < K; k0 += 8) {
        float4 av, bv;
        const bool has_next = (k0 + 8) < K;
        if (has_next) {
            av = *(const float4*)(Ap + k0 + 8);
            bv = *(const float4*)(Wp + (size_t)(k0 + 8) * N);
        }
#pragma unroll
        for (int kk = 0; kk < 8; ++kk) {
            float4 a0 = *(const float4*)&As[buf][kk][ty * 8];
            float4 a1 = *(const float4*)&As[buf][kk][ty * 8 + 4];
            ulonglong2 b01 = *(const ulonglong2*)&Bs[buf][kk][tx * 8];
            ulonglong2 b23 = *(const ulonglong2*)&Bs[buf][kk][tx * 8 + 4];
            unsigned long long b2[4] = {b01.x, b01.y, b23.x, b23.y};
            float ar[8] = {a0.x, a0.y, a0.z, a0.w, a1.x, a1.y, a1.z, a1.w};
#pragma unroll
            for (int i = 0; i < 8; ++i) {
                unsigned long long pa = pack2(ar[i]);
#pragma unroll
                for (int jp = 0; jp < 4; ++jp) FFMA2(acc2[i][jp], pa, b2[jp]);
            }
        }
        if (has_next) {
            const int nb = buf ^ 1;
            As[nb][acol + 0][arow] = av.x;
            As[nb][acol + 1][arow] = av.y;
            As[nb][acol + 2][arow] = av.z;
            As[nb][acol + 3][arow] = av.w;
            *(float4*)&Bs[nb][brow][bcol] = bv;
            __syncthreads();
            buf = nb;
        }
    }

#pragma unroll
    for (int i = 0; i < 8; ++i) {
        int r = m0 + ty * 8 + i;
        float accf[8];
#pragma unroll
        for (int jp = 0; jp < 4; ++jp) unpack2(acc2[i][jp], accf[2 * jp], accf[2 * jp + 1]);
#pragma unroll
        for (int j = 0; j < 8; ++j) {
            int c = n0 + tx * 8 + j;
            float v = accf[j] + bias[c];
            int bb = r / T, tl = r - bb * T;
            int h = c >> 6, d = c & 63;
            C[((size_t)((bb * Hn + h) * T + tl) << 6) + d] = v;
        }
    }
}

// ---------------------------------------------------------------------------
// bf16x2 split of ctx activations: A -> 2 bf16 planes in g_Asp (stride MK).
// ---------------------------------------------------------------------------
__global__ void split_A_k(const float* __restrict__ A, size_t MK)
{
    for (size_t i = ((size_t)blockIdx.x * 256 + threadIdx.x) * 2; i < MK;
         i += (size_t)gridDim.x * 512) {
        float2 f = *(const float2*)(A + i);
        __nv_bfloat16 ax1 = __float2bfloat16(f.x);
        __nv_bfloat16 ax2 = __float2bfloat16(f.x - __bfloat162float(ax1));
        __nv_bfloat16 ay1 = __float2bfloat16(f.y);
        __nv_bfloat16 ay2 = __float2bfloat16(f.y - __bfloat162float(ay1));
        *(__nv_bfloat162*)(g_Asp + i)      = __nv_bfloat162(ax1, ay1);
        *(__nv_bfloat162*)(g_Asp + MK + i) = __nv_bfloat162(ax2, ay2);
    }
}

// ---------------------------------------------------------------------------
// W split + transpose: W[K][1024] f32 -> g_Ws[WIDX] 2 bf16 planes [1024][K].
// ---------------------------------------------------------------------------
template <int WIDX>
__global__ void split_W_k(const float* __restrict__ W, int K)
{
    __shared__ float t[32][33];
    const int k0 = blockIdx.y * 32, n0 = blockIdx.x * 32;
    const int tx = threadIdx.x, ty = threadIdx.y;   // (32, 8)
#pragma unroll
    for (int i = 0; i < 4; ++i)
        t[ty + 8 * i][tx] = W[(size_t)(k0 + ty + 8 * i) * 1024 + n0 + tx];
    __syncthreads();
    __nv_bfloat16* P = g_Ws[WIDX];
    const size_t NK = (size_t)1024 * K;
#pragma unroll
    for (int i = 0; i < 4; ++i) {
        int n = ty + 8 * i;
        float f = t[tx][n];                          // = W[k0+tx][n0+n]
        __nv_bfloat16 b1 = __float2bfloat16(f);
        __nv_bfloat16 b2 = __float2bfloat16(f - __bfloat162float(b1));
        size_t o = (size_t)(n0 + n) * K + k0 + tx;
        P[o] = b1; P[NK + o] = b2;
    }
}

// ---------------------------------------------------------------------------
// wmma bf16x2 GEMM: C[M,1024] = A @ W + bias via 3 split products
// (A1B1 + A1B2 + A2B1) folded into one extended-K loop. Tile 128m x 64n x 32k,
// 8 warps (4m x 2n), HMMA m16n16k16 bf16->f32, double-buffered smem.
// DST 2: head-scatter to g_V; DST 4: plain out.
// ---------------------------------------------------------------------------
template <int DST>
__global__ __launch_bounds__(256, 2) void wmma_gemm(
    const float* __restrict__ bias, float* __restrict__ Cext, int M, int K, int T)
{
    // A: 2 bufs x [128][40] bf16 (10240B); B: 2 bufs x [64][40] (5120B)
    __shared__ __align__(16) unsigned char smraw[30720];
    __shared__ float sbias[64];

    const int tid = threadIdx.x, wid = tid >> 5;
    const int wm = wid & 3, wn = wid >> 2;
    const int n0 = blockIdx.x * 64, m0 = blockIdx.y * 128;

    auto Arow = [&](int buf, int r) -> __nv_bfloat16* {
        return (__nv_bfloat16*)(smraw + buf * 10240 + r * 80);
    };
    auto Brow = [&](int buf, int r) -> __nv_bfloat16* {
        return (__nv_bfloat16*)(smraw + 20480 + buf * 5120 + r * 80);
    };

    if (tid < 64) sbias[tid] = bias[n0 + tid];

    const int WIDX = (DST == 2) ? 0 : 1;
    const __nv_bfloat16* Wt = g_Ws[WIDX];
    const size_t MK = (size_t)M * K, NK = (size_t)1024 * K;
    const int kch = K >> 5, nch = 3 * kch;
    const int PA[3] = {0, 0, 1};
    const int PB[3] = {0, 1, 0};

    wmma::fragment<wmma::accumulator, 16, 16, 16, float> acc[2][2];
#pragma unroll
    for (int i = 0; i < 2; ++i)
#pragma unroll
        for (int j = 0; j < 2; ++j) wmma::fill_fragment(acc[i][j], 0.f);

    {   // prologue: chunk 0 (planes A0/B0, ko=0)
        const __nv_bfloat16* gA = g_Asp + (size_t)m0 * K;
        const __nv_bfloat16* gB = Wt + (size_t)n0 * K;
#pragma unroll
        for (int u = 0; u < 2; ++u) {
            int idx = u * 256 + tid, row = idx >> 2, c8 = idx & 3;
            uint4 v = *(const uint4*)(gA + (size_t)row * K + c8 * 8);
            *(uint4*)(Arow(0, row) + c8 * 8) = v;
        }
        {
            int row = tid >> 2, c8 = tid & 3;
            uint4 v = *(const uint4*)(gB + (size_t)row * K + c8 * 8);
            *(uint4*)(Brow(0, row) + c8 * 8) = v;
        }
    }
    __syncthreads();

    int buf = 0;
    for (int c = 0; c < nch; ++c) {
        uint4 va0, va1, vb;
        const bool has_next = (c + 1) < nch;
        if (has_next) {
            const int cn = c + 1, sub = cn / kch, ko = (cn - sub * kch) << 5;
            const __nv_bfloat16* gA = g_Asp + (size_t)PA[sub] * MK + (size_t)m0 * K + ko;
            const __nv_bfloat16* gB = Wt + (size_t)PB[sub] * NK + (size_t)n0 * K + ko;
            {
                int i0 = tid, r = i0 >> 2, c8 = i0 & 3;
                va0 = *(const uint4*)(gA + (size_t)r * K + c8 * 8);
            }
            {
                int i1 = 256 + tid, r = i1 >> 2, c8 = i1 & 3;
                va1 = *(const uint4*)(gA + (size_t)r * K + c8 * 8);
            }
            {
                int r = tid >> 2, c8 = tid & 3;
                vb = *(const uint4*)(gB + (size_t)r * K + c8 * 8);
            }
        }

#pragma unroll
        for (int ks = 0; ks < 2; ++ks) {
            wmma::fragment<wmma::matrix_a, 16, 16, 16, __nv_bfloat16, wmma::row_major> af[2];
            wmma::fragment<wmma::matrix_b, 16, 16, 16, __nv_bfloat16, wmma::col_major> bf[2];
#pragma unroll
            for (int mi = 0; mi < 2; ++mi)
                wmma::load_matrix_sync(af[mi], Arow(buf, wm * 32 + mi * 16) + ks * 16, 40);
#pragma unroll
            for (int ni = 0; ni < 2; ++ni)
                wmma::load_matrix_sync(bf[ni], Brow(buf, wn * 32 + ni * 16) + ks * 16, 40);
#pragma unroll
            for (int mi = 0; mi < 2; ++mi)
#pragma unroll
                for (int ni = 0; ni < 2; ++ni)
                    wmma::mma_sync(acc[mi][ni], af[mi], bf[ni], acc[mi][ni]);
        }

        if (has_next) {
            const int nb = buf ^ 1;
            {
                int i0 = tid, r = i0 >> 2, c8 = i0 & 3;
                *(uint4*)(Arow(nb, r) + c8 * 8) = va0;
            }
            {
                int i1 = 256 + tid, r = i1 >> 2, c8 = i1 & 3;
                *(uint4*)(Arow(nb, r) + c8 * 8) = va1;
            }
            {
                int r = tid >> 2, c8 = tid & 3;
                *(uint4*)(Brow(nb, r) + c8 * 8) = vb;
            }
            __syncthreads();
            buf = nb;
        }
    }

    // epilogue: two half-passes through smem (reuse smraw as float [128][36])
    float (*Cs)[36] = (float (*)[36])smraw;
    const int r = tid >> 1, hc = (tid & 1) * 16;
    const int m = m0 + r;
    float* dst;
    if (DST == 2) {
        int bb = m / T, tl = m - bb * T, h = n0 >> 6;
        dst = g_V + ((size_t)((bb * Hn + h) * T + tl) << 6);
    } else {
        dst = Cext + (size_t)m * 1024 + n0;
    }

#pragma unroll
    for (int p = 0; p < 2; ++p) {
        __syncthreads();
        if (wn == p) {
#pragma unroll
            for (int mi = 0; mi < 2; ++mi)
#pragma unroll
                for (int ni = 0; ni < 2; ++ni)
                    wmma::store_matrix_sync(&Cs[wm * 32 + mi * 16][ni * 16],
                                            acc[mi][ni], 36, wmma::mem_row_major);
        }
        __syncthreads();
#pragma unroll
        for (int j4 = 0; j4 < 4; ++j4) {
            int cc = hc + j4 * 4;
            float4 v;
            v.x = Cs[r][cc + 0] + sbias[p * 32 + cc + 0];
            v.y = Cs[r][cc + 1] + sbias[p * 32 + cc + 1];
            v.z = Cs[r][cc + 2] + sbias[p * 32 + cc + 2];
            v.w = Cs[r][cc + 3] + sbias[p * 32 + cc + 3];
            *(float4*)(dst + p * 32 + cc) = v;
        }
    }
}

// ---------------------------------------------------------------------------
// QK^T logits GEMM (bitwise-identical to rounds 4-11)
// ---------------------------------------------------------------------------
__global__ __launch_bounds__(256, 2) void qk_logits_k(const void* __restrict__ mask)
{
    extern __shared__ float sm[];
    float (*Qs)[132] = (float (*)[132])sm;
    float (*Ks)[132] = (float (*)[132])(sm + 64 * 132);

    const int tid = threadIdx.x;
    const int bh = blockIdx.z;
    const int q0 = blockIdx.y * 128, n0 = blockIdx.x * 128;
    const float* Qb = g_Q + ((size_t)bh * TQn + q0) * 64;
    const float* Kb = g_K + ((size_t)bh * TKn + n0) * 64;

    {
        const int m = tid & 127, half = tid >> 7;
#pragma unroll
        for (int cc = 0; cc < 8; ++cc) {
            const int d4 = half + 2 * cc;
            float4 qv = *(const float4*)(Qb + (size_t)m * 64 + d4 * 4);
            Qs[d4 * 4 + 0][m] = qv.x * 0.125f;
            Qs[d4 * 4 + 1][m] = qv.y * 0.125f;
            Qs[d4 * 4 + 2][m] = qv.z * 0.125f;
            Qs[d4 * 4 + 3][m] = qv.w * 0.125f;
            float4 kv = *(const float4*)(Kb + (size_t)m * 64 + d4 * 4);
            Ks[d4 * 4 + 0][m] = kv.x;
            Ks[d4 * 4 + 1][m] = kv.y;
            Ks[d4 * 4 + 2][m] = kv.z;
            Ks[d4 * 4 + 3][m] = kv.w;
        }
    }
    __syncthreads();

    const int tx = tid & 15, ty = tid >> 4;
    unsigned long long acc2[8][4];
#pragma unroll
    for (int i = 0; i < 8; ++i)
#pragma unroll
        for (int jp = 0; jp < 4; ++jp) acc2[i][jp] = 0ull;

#pragma unroll 8
    for (int kk = 0; kk < 64; ++kk) {
        float4 a0 = *(const float4*)&Qs[kk][ty * 8];
        float4 a1 = *(const float4*)&Qs[kk][ty * 8 + 4];
        ulonglong2 b01 = *(const ulonglong2*)&Ks[kk][tx * 8];
        ulonglong2 b23 = *(const ulonglong2*)&Ks[kk][tx * 8 + 4];
        unsigned long long b2[4] = {b01.x, b01.y, b23.x, b23.y};
        float ar[8] = {a0.x, a0.y, a0.z, a0.w, a1.x, a1.y, a1.z, a1.w};
#pragma unroll
        for (int i = 0; i < 8; ++i) {
            unsigned long long pa = pack2(ar[i]);
#pragma unroll
            for (int jp = 0; jp < 4; ++jp) FFMA2(acc2[i][jp], pa, b2[jp]);
        }
    }

    const int mode = g_mask_mode, b = bh >> 4;
    unsigned char mku[8];
#pragma unroll
    for (int j = 0; j < 8; ++j) mku[j] = mask_at(mask, mode, b * TKn + n0 + tx * 8 + j);

#pragma unroll
    for (int i = 0; i < 8; ++i) {
        float* Lp = g_L + ((size_t)bh * TQn + q0 + ty * 8 + i) * TKn + n0 + tx * 8;
        float o[8];
#pragma unroll
        for (int jp = 0; jp < 4; ++jp) unpack2(acc2[i][jp], o[2 * jp], o[2 * jp + 1]);
#pragma unroll
        for (int j = 0; j < 8; ++j) if (mku[j]) o[j] = NEG_BIG;
        __stcs((float4*)Lp,       make_float4(o[0], o[1], o[2], o[3]));
        __stcs((float4*)(Lp + 4), make_float4(o[4], o[5], o[6], o[7]));
    }
}

// ---------------------------------------------------------------------------
// Top-64 + softmax + sparse AV (unchanged from round 11)
// ---------------------------------------------------------------------------
__device__ __forceinline__ int cnt_ge(const float (&a)[64], float t)
{
    int c = 0;
#pragma unroll
    for (int j = 0; j < 64; ++j) c += (a[j] >= t) ? 1 : 0;
    return __reduce_add_sync(0xffffffffu, c);
}

__global__ __launch_bounds__(256, 2) void topk_av_k()
{
    __shared__ int   skey[8][80];
    __shared__ float swgt[8][80];

    const int lane = threadIdx.x & 31, w = threadIdx.x >> 5;
    const int b = blockIdx.z, h = blockIdx.y;
    const int bh = b * Hn + h;
    const int q = blockIdx.x * 8 + w;

    const float* Lq = g_L + ((size_t)bh * TQn + q) * TKn;
    float acc[64];
#pragma unroll
    for (int j = 0; j < 64; ++j) acc[j] = __ldcs(Lq + j * 32 + lane);

    float m = NEG_BIG;
#pragma unroll
    for (int j = 0; j < 64; ++j) m = fmaxf(m, acc[j]);
#pragma unroll
    for (int o = 16; o > 0; o >>= 1) m = fmaxf(m, __shfl_xor_sync(0xffffffffu, m, o));

    // bracketing: lo has cnt>=64, hi has cnt<64 (hi=m assumed cnt~1)
    float lo = m - 32.0f, hi = m;
    int clo = cnt_ge(acc, lo), chi = 1;
    int guard = 0;
    while (clo < 64 && guard++ < 90) { lo = m - 2.0f * (m - lo); clo = cnt_ge(acc, lo); }

    for (int it = 0; it < 32 && clo != 64; ++it) {
        float t;
        if (it == 0) {
            t = m - 1.9f;
        } else {
            float f = (__logf(64.f) - __logf((float)chi)) /
                      (__logf((float)clo) - __logf((float)chi));
            t = hi + f * (lo - hi);
        }
        if (!(t > lo && t < hi)) t = 0.5f * (lo + hi);
        if (!(t > lo && t < hi)) break;
        int c2 = cnt_ge(acc, t);
        if (c2 >= 64) { lo = t; clo = c2; } else { hi = t; chi = c2; }
    }
    const float thr = lo;

    int base = 0;
#pragma unroll
    for (int j = 0; j < 64; ++j) {
        bool sel = acc[j] >= thr;
        unsigned bal = __ballot_sync(0xffffffffu, sel);
        if (sel) {
            int pos = base + __popc(bal & ((1u << lane) - 1u));
            if (pos < 80) {
                skey[w][pos] = j * 32 + lane;
                swgt[w][pos] = __expf(acc[j] - m);
            }
        }
        base += __popc(bal);
    }
    const int nsel = base < 80 ? base : 80;
    __syncwarp();

    float z = 0.f;
    for (int i = lane; i < nsel; i += 32) z += swgt[w][i];
#pragma unroll
    for (int o = 16; o > 0; o >>= 1) z += __shfl_xor_sync(0xffffffffu, z, o);

    const float* Vb = g_V + (size_t)bh * TKn * 64;
    float o0 = 0.f, o1 = 0.f;
    int i = 0;
    for (; i + 8 <= nsel; i += 8) {
        int   kv[8]; float wv[8];
#pragma unroll
        for (int u = 0; u < 8; ++u) { kv[u] = skey[w][i + u]; wv[u] = swgt[w][i + u]; }
        float2 vv[8];
#pragma unroll
        for (int u = 0; u < 8; ++u)
            vv[u] = *(const float2*)(Vb + (size_t)kv[u] * 64 + 2 * lane);
#pragma unroll
        for (int u = 0; u < 8; ++u) { o0 += wv[u] * vv[u].x; o1 += wv[u] * vv[u].y; }
    }
    for (; i < nsel; ++i) {
        float wv = swgt[w][i];
        float2 vv = *(const float2*)(Vb + (size_t)skey[w][i] * 64 + 2 * lane);
        o0 += wv * vv.x;
        o1 += wv * vv.y;
    }

    // epilogue: normalized output -> bf16x2 split planes (fused split_A)
    const float inv = 1.0f / z;
    const float r0 = o0 * inv, r1 = o1 * inv;
    __nv_bfloat16 x1 = __float2bfloat16(r0);
    __nv_bfloat16 x2 = __float2bfloat16(r0 - __bfloat162float(x1));
    __nv_bfloat16 y1 = __float2bfloat16(r1);
    __nv_bfloat16 y2 = __float2bfloat16(r1 - __bfloat162float(y1));
    const size_t MK = (size_t)Bb * TQn * DQn;
    const size_t o = ((size_t)(b * TQn + q)) * DQn + h * 64 + 2 * lane;
    *(__nv_bfloat162*)(g_Asp + o)      = __nv_bfloat162(x1, y1);
    *(__nv_bfloat162*)(g_Asp + MK + o) = __nv_bfloat162(x2, y2);
}

// ---------------------------------------------------------------------------
extern "C" void kernel_launch(void* const* d_in, const int* in_sizes, int n_in,
                              void* d_out, int out_size)
{
    const float* x   = (const float*)d_in[0];
    const float* ctx = (const float*)d_in[1];
    const void*  msk = d_in[2];
    const float* Wq = (const float*)d_in[3];
    const float* bq = (const float*)d_in[4];
    const float* Wk = (const float*)d_in[5];
    const float* bk = (const float*)d_in[6];
    const float* Wv = (const float*)d_in[7];
    const float* bv = (const float*)d_in[8];
    const float* Wo = (const float*)d_in[9];
    const float* bo = (const float*)d_in[10];
    float* out = (float*)d_out;

    const int qk_smem = 2 * 64 * 132 * sizeof(float);   // 67.6 KB
    static bool attr_done = false;
    if (!attr_done) {
        cudaFuncSetAttribute(qk_logits_k, cudaFuncAttributeMaxDynamicSharedMemorySize, qk_smem);
        attr_done = true;
    }

    detect_mask_kernel<<<1, 256>>>((const unsigned char*)msk);

    // Q + K projections batched in one launch (wave-packed, 384 CTAs)
    qkproj_k<<<384, 256>>>(x, Wq, bq, ctx, Wk, bk);

    // V projection: wmma bf16x2 (selection-independent)
    split_W_k<0><<<dim3(32, 24), dim3(32, 8)>>>(Wv, 768);
    split_W_k<1><<<dim3(32, 32), dim3(32, 8)>>>(Wo, 1024);
    split_A_k<<<4096, 256>>>(ctx, (size_t)4096 * 768);
    wmma_gemm<2><<<dim3(16, 32), 256>>>(bv, nullptr, 4096, 768, 2048);

    // masked logits (bitwise-identical)
    qk_logits_k<<<dim3(TKn / 128, TQn / 128, Bb * Hn), 256, qk_smem>>>(msk);
    // top-64 + softmax + sparse AV (writes bf16 split planes directly)
    topk_av_k<<<dim3(TQn / 8, Hn, Bb), 256>>>();

    // output projection: wmma bf16x2 (reads planes written by topk_av_k)
    wmma_gemm<4><<<dim3(16, 16), 256>>>(bo, out, 2048, 1024, 1024);
}

// round 13
// speedup vs baseline: 1.0171x; 1.0171x over previous
#include <cuda_runtime.h>
#include <cuda_bf16.h>
#include <mma.h>
#include <math.h>
#include <float.h>

using namespace nvcuda;

#define NEG_BIG (-3.402823466e38f)

constexpr int Bb = 2, TQn = 1024, TKn = 2048, DQn = 1024, DCn = 768, Hn = 16, DHn = 64;

// Scratch (allocation-free rule: __device__ globals), referenced only in device code.
__device__ float g_Q[Bb * Hn * TQn * DHn];          // (b,h,q,d)   8 MB
__device__ float g_K[Bb * Hn * TKn * DHn];          // (b,h,k,d)  16 MB
__device__ float g_V[Bb * Hn * TKn * DHn];          // (b,h,k,d)  16 MB
__device__ float g_L[(size_t)Bb * Hn * TQn * TKn];  // logits 256 MB
__device__ int   g_mask_mode;
// bf16x2 split planes (V / out projections only — selection-independent)
__device__ __nv_bfloat16 g_Asp[2ull * 4096 * 1024];     // activation splits
__device__ __nv_bfloat16 g_Ws[2][2ull * 1024 * 1024];   // transposed weight splits [n][k]: 0=Wv, 1=Wo

// ---------------- packed f32x2 helpers ----------------
__device__ __forceinline__ unsigned long long pack2(float x) {
    unsigned long long r; asm("mov.b64 %0, {%1, %1};" : "=l"(r) : "f"(x)); return r;
}
#define FFMA2(acc, a, b) asm("fma.rn.f32x2 %0, %1, %2, %0;" : "+l"(acc) : "l"(a), "l"(b))
__device__ __forceinline__ void unpack2(unsigned long long v, float& lo, float& hi) {
    asm("mov.b64 {%0, %1}, %2;" : "=f"(lo), "=f"(hi) : "l"(v));
}

// ---------------------------------------------------------------------------
// Mask dtype detection
// ---------------------------------------------------------------------------
__global__ void detect_mask_kernel(const unsigned char* __restrict__ m)
{
    __shared__ int s_big, s_mis;
    if (threadIdx.x == 0) { s_big = 0; s_mis = 0; }
    __syncthreads();
    int big = 0, mis = 0;
    for (int i = threadIdx.x; i < Bb * TKn; i += 256) {
        unsigned char v = m[i];
        if (v > 1) big = 1;
        else if (v == 1 && (i & 3)) mis = 1;
    }
    if (big) atomicOr(&s_big, 1);
    if (mis) atomicOr(&s_mis, 1);
    __syncthreads();
    if (threadIdx.x == 0) g_mask_mode = s_big ? 2 : (s_mis ? 0 : 1);
}

__device__ __forceinline__ unsigned char mask_at(const void* mask, int mode, int idx)
{
    if (mode == 2) return ((const float*)mask)[idx] != 0.f;
    if (mode == 1) return ((const int*)mask)[idx] != 0;
    return ((const unsigned char*)mask)[idx];
}

// ---------------------------------------------------------------------------
// Q+K projection, one launch, compile-time dual body (register-clean merge).
// PATH 0: x @ Wq + bq -> g_Q (K=1024, T=TQn); PATH 1: ctx @ Wk + bk -> g_K
// (K=768, T=TKn). Each instantiation is codegen-identical to the round-6
// proven gemm_k (bitwise accumulation chains).
// ---------------------------------------------------------------------------
template <int PATH>
__device__ __forceinline__ void qkproj_body(
    const float* __restrict__ A, const float* __restrict__ W,
    const float* __restrict__ bias, int cid,
    float (&As)[2][8][128], float (&Bs)[2][8][132])
{
    constexpr int K = (PATH == 0) ? 1024 : 768;
    constexpr int T = (PATH == 0) ? TQn : TKn;
    constexpr int N = 1024;
    float* C = (PATH == 0) ? g_Q : g_K;

    const int tid = threadIdx.x;
    const int tx = tid & 15, ty = tid >> 4;
    const int m0 = (cid >> 3) * 128, n0 = (cid & 7) * 128;

    unsigned long long acc2[8][4];
#pragma unroll
    for (int i = 0; i < 8; ++i)
#pragma unroll
        for (int jp = 0; jp < 4; ++jp) acc2[i][jp] = 0ull;

    const int arow = tid >> 1, acol = (tid & 1) * 4;
    const int brow = tid >> 5, bcol = (tid & 31) * 4;
    const float* Ap = A + (size_t)(m0 + arow) * K + acol;
    const float* Wp = W + (size_t)brow * N + n0 + bcol;

    {
        float4 av = *(const float4*)(Ap);
        float4 bv = *(const float4*)(Wp);
        As[0][acol + 0][arow] = av.x;
        As[0][acol + 1][arow] = av.y;
        As[0][acol + 2][arow] = av.z;
        As[0][acol + 3][arow] = av.w;
        *(float4*)&Bs[0][brow][bcol] = bv;
    }
    __syncthreads();

    int buf = 0;
    for (int k0 = 0; k0 < K; k0 += 8) {
        float4 av, bv;
        const bool has_next = (k0 + 8) < K;
        if (has_next) {
            av = *(const float4*)(Ap + k0 + 8);
            bv = *(const float4*)(Wp + (size_t)(k0 + 8) * N);
        }
#pragma unroll
        for (int kk = 0; kk < 8; ++kk) {
            float4 a0 = *(const float4*)&As[buf][kk][ty * 8];
            float4 a1 = *(const float4*)&As[buf][kk][ty * 8 + 4];
            ulonglong2 b01 = *(const ulonglong2*)&Bs[buf][kk][tx * 8];
            ulonglong2 b23 = *(const ulonglong2*)&Bs[buf][kk][tx * 8 + 4];
            unsigned long long b2[4] = {b01.x, b01.y, b23.x, b23.y};
            float ar[8] = {a0.x, a0.y, a0.z, a0.w, a1.x, a1.y, a1.z, a1.w};
#pragma unroll
            for (int i = 0; i < 8; ++i) {
                unsigned long long pa = pack2(ar[i]);
#pragma unroll
                for (int jp = 0; jp < 4; ++jp) FFMA2(acc2[i][jp], pa, b2[jp]);
            }
        }
        if (has_next) {
            const int nb = buf ^ 1;
            As[nb][acol + 0][arow] = av.x;
            As[nb][acol + 1][arow] = av.y;
            As[nb][acol + 2][arow] = av.z;
            As[nb][acol + 3][arow] = av.w;
            *(float4*)&Bs[nb][brow][bcol] = bv;
            __syncthreads();
            buf = nb;
        }
    }

#pragma unroll
    for (int i = 0; i < 8; ++i) {
        int r = m0 + ty * 8 + i;
        float accf[8];
#pragma unroll
        for (int jp = 0; jp < 4; ++jp) unpack2(acc2[i][jp], accf[2 * jp], accf[2 * jp + 1]);
#pragma unroll
        for (int j = 0; j < 8; ++j) {
            int c = n0 + tx * 8 + j;
            float v = accf[j] + bias[c];
            int bb = r / T, tl = r - bb * T;
            int h = c >> 6, d = c & 63;
            C[((size_t)((bb * Hn + h) * T + tl) << 6) + d] = v;
        }
    }
}

__global__ __launch_bounds__(256, 2) void qkproj_k(
    const float* __restrict__ x,   const float* __restrict__ Wq, const float* __restrict__ bq,
    const float* __restrict__ ctx, const float* __restrict__ Wk, const float* __restrict__ bk)
{
    __shared__ float As[2][8][128];
    __shared__ float Bs[2][8][132];
    if (blockIdx.x < 128) qkproj_body<0>(x,   Wq, bq, blockIdx.x,       As, Bs);
    else                  qkproj_body<1>(ctx, Wk, bk, blockIdx.x - 128, As, Bs);
}

// ---------------------------------------------------------------------------
// bf16x2 split of ctx activations: A -> 2 bf16 planes in g_Asp (stride MK).
// ---------------------------------------------------------------------------
__global__ void split_A_k(const float* __restrict__ A, size_t MK)
{
    for (size_t i = ((size_t)blockIdx.x * 256 + threadIdx.x) * 2; i < MK;
         i += (size_t)gridDim.x * 512) {
        float2 f = *(const float2*)(A + i);
        __nv_bfloat16 ax1 = __float2bfloat16(f.x);
        __nv_bfloat16 ax2 = __float2bfloat16(f.x - __bfloat162float(ax1));
        __nv_bfloat16 ay1 = __float2bfloat16(f.y);
        __nv_bfloat16 ay2 = __float2bfloat16(f.y - __bfloat162float(ay1));
        *(__nv_bfloat162*)(g_Asp + i)      = __nv_bfloat162(ax1, ay1);
        *(__nv_bfloat162*)(g_Asp + MK + i) = __nv_bfloat162(ax2, ay2);
    }
}

// ---------------------------------------------------------------------------
// W split + transpose: W[K][1024] f32 -> g_Ws[WIDX] 2 bf16 planes [1024][K].
// ---------------------------------------------------------------------------
template <int WIDX>
__global__ void split_W_k(const float* __restrict__ W, int K)
{
    __shared__ float t[32][33];
    const int k0 = blockIdx.y * 32, n0 = blockIdx.x * 32;
    const int tx = threadIdx.x, ty = threadIdx.y;   // (32, 8)
#pragma unroll
    for (int i = 0; i < 4; ++i)
        t[ty + 8 * i][tx] = W[(size_t)(k0 + ty + 8 * i) * 1024 + n0 + tx];
    __syncthreads();
    __nv_bfloat16* P = g_Ws[WIDX];
    const size_t NK = (size_t)1024 * K;
#pragma unroll
    for (int i = 0; i < 4; ++i) {
        int n = ty + 8 * i;
        float f = t[tx][n];                          // = W[k0+tx][n0+n]
        __nv_bfloat16 b1 = __float2bfloat16(f);
        __nv_bfloat16 b2 = __float2bfloat16(f - __bfloat162float(b1));
        size_t o = (size_t)(n0 + n) * K + k0 + tx;
        P[o] = b1; P[NK + o] = b2;
    }
}

// ---------------------------------------------------------------------------
// wmma bf16x2 GEMM: C[M,1024] = A @ W + bias via 3 split products
// (A1B1 + A1B2 + A2B1) folded into one extended-K loop. Tile 128m x 64n x 32k,
// 8 warps (4m x 2n), HMMA m16n16k16 bf16->f32, double-buffered smem.
// DST 2: head-scatter to g_V; DST 4: plain out.
// ---------------------------------------------------------------------------
template <int DST>
__global__ __launch_bounds__(256, 2) void wmma_gemm(
    const float* __restrict__ bias, float* __restrict__ Cext, int M, int K, int T)
{
    // A: 2 bufs x [128][40] bf16 (10240B); B: 2 bufs x [64][40] (5120B)
    __shared__ __align__(16) unsigned char smraw[30720];
    __shared__ float sbias[64];

    const int tid = threadIdx.x, wid = tid >> 5;
    const int wm = wid & 3, wn = wid >> 2;
    const int n0 = blockIdx.x * 64, m0 = blockIdx.y * 128;

    auto Arow = [&](int buf, int r) -> __nv_bfloat16* {
        return (__nv_bfloat16*)(smraw + buf * 10240 + r * 80);
    };
    auto Brow = [&](int buf, int r) -> __nv_bfloat16* {
        return (__nv_bfloat16*)(smraw + 20480 + buf * 5120 + r * 80);
    };

    if (tid < 64) sbias[tid] = bias[n0 + tid];

    const int WIDX = (DST == 2) ? 0 : 1;
    const __nv_bfloat16* Wt = g_Ws[WIDX];
    const size_t MK = (size_t)M * K, NK = (size_t)1024 * K;
    const int kch = K >> 5, nch = 3 * kch;
    const int PA[3] = {0, 0, 1};
    const int PB[3] = {0, 1, 0};

    wmma::fragment<wmma::accumulator, 16, 16, 16, float> acc[2][2];
#pragma unroll
    for (int i = 0; i < 2; ++i)
#pragma unroll
        for (int j = 0; j < 2; ++j) wmma::fill_fragment(acc[i][j], 0.f);

    {   // prologue: chunk 0 (planes A0/B0, ko=0)
        const __nv_bfloat16* gA = g_Asp + (size_t)m0 * K;
        const __nv_bfloat16* gB = Wt + (size_t)n0 * K;
#pragma unroll
        for (int u = 0; u < 2; ++u) {
            int idx = u * 256 + tid, row = idx >> 2, c8 = idx & 3;
            uint4 v = *(const uint4*)(gA + (size_t)row * K + c8 * 8);
            *(uint4*)(Arow(0, row) + c8 * 8) = v;
        }
        {
            int row = tid >> 2, c8 = tid & 3;
            uint4 v = *(const uint4*)(gB + (size_t)row * K + c8 * 8);
            *(uint4*)(Brow(0, row) + c8 * 8) = v;
        }
    }
    __syncthreads();

    int buf = 0;
    for (int c = 0; c < nch; ++c) {
        uint4 va0, va1, vb;
        const bool has_next = (c + 1) < nch;
        if (has_next) {
            const int cn = c + 1, sub = cn / kch, ko = (cn - sub * kch) << 5;
            const __nv_bfloat16* gA = g_Asp + (size_t)PA[sub] * MK + (size_t)m0 * K + ko;
            const __nv_bfloat16* gB = Wt + (size_t)PB[sub] * NK + (size_t)n0 * K + ko;
            {
                int i0 = tid, r = i0 >> 2, c8 = i0 & 3;
                va0 = *(const uint4*)(gA + (size_t)r * K + c8 * 8);
            }
            {
                int i1 = 256 + tid, r = i1 >> 2, c8 = i1 & 3;
                va1 = *(const uint4*)(gA + (size_t)r * K + c8 * 8);
            }
            {
                int r = tid >> 2, c8 = tid & 3;
                vb = *(const uint4*)(gB + (size_t)r * K + c8 * 8);
            }
        }

#pragma unroll
        for (int ks = 0; ks < 2; ++ks) {
            wmma::fragment<wmma::matrix_a, 16, 16, 16, __nv_bfloat16, wmma::row_major> af[2];
            wmma::fragment<wmma::matrix_b, 16, 16, 16, __nv_bfloat16, wmma::col_major> bf[2];
#pragma unroll
            for (int mi = 0; mi < 2; ++mi)
                wmma::load_matrix_sync(af[mi], Arow(buf, wm * 32 + mi * 16) + ks * 16, 40);
#pragma unroll
            for (int ni = 0; ni < 2; ++ni)
                wmma::load_matrix_sync(bf[ni], Brow(buf, wn * 32 + ni * 16) + ks * 16, 40);
#pragma unroll
            for (int mi = 0; mi < 2; ++mi)
#pragma unroll
                for (int ni = 0; ni < 2; ++ni)
                    wmma::mma_sync(acc[mi][ni], af[mi], bf[ni], acc[mi][ni]);
        }

        if (has_next) {
            const int nb = buf ^ 1;
            {
                int i0 = tid, r = i0 >> 2, c8 = i0 & 3;
                *(uint4*)(Arow(nb, r) + c8 * 8) = va0;
            }
            {
                int i1 = 256 + tid, r = i1 >> 2, c8 = i1 & 3;
                *(uint4*)(Arow(nb, r) + c8 * 8) = va1;
            }
            {
                int r = tid >> 2, c8 = tid & 3;
                *(uint4*)(Brow(nb, r) + c8 * 8) = vb;
            }
            __syncthreads();
            buf = nb;
        }
    }

    // epilogue: two half-passes through smem (reuse smraw as float [128][36])
    float (*Cs)[36] = (float (*)[36])smraw;
    const int r = tid >> 1, hc = (tid & 1) * 16;
    const int m = m0 + r;
    float* dst;
    if (DST == 2) {
        int bb = m / T, tl = m - bb * T, h = n0 >> 6;
        dst = g_V + ((size_t)((bb * Hn + h) * T + tl) << 6);
    } else {
        dst = Cext + (size_t)m * 1024 + n0;
    }

#pragma unroll
    for (int p = 0; p < 2; ++p) {
        __syncthreads();
        if (wn == p) {
#pragma unroll
            for (int mi = 0; mi < 2; ++mi)
#pragma unroll
                for (int ni = 0; ni < 2; ++ni)
                    wmma::store_matrix_sync(&Cs[wm * 32 + mi * 16][ni * 16],
                                            acc[mi][ni], 36, wmma::mem_row_major);
        }
        __syncthreads();
#pragma unroll
        for (int j4 = 0; j4 < 4; ++j4) {
            int cc = hc + j4 * 4;
            float4 v;
            v.x = Cs[r][cc + 0] + sbias[p * 32 + cc + 0];
            v.y = Cs[r][cc + 1] + sbias[p * 32 + cc + 1];
            v.z = Cs[r][cc + 2] + sbias[p * 32 + cc + 2];
            v.w = Cs[r][cc + 3] + sbias[p * 32 + cc + 3];
            *(float4*)(dst + p * 32 + cc) = v;
        }
    }
}

// ---------------------------------------------------------------------------
// QK^T logits GEMM (bitwise-identical to rounds 4-12)
// ---------------------------------------------------------------------------
__global__ __launch_bounds__(256, 2) void qk_logits_k(const void* __restrict__ mask)
{
    extern __shared__ float sm[];
    float (*Qs)[132] = (float (*)[132])sm;
    float (*Ks)[132] = (float (*)[132])(sm + 64 * 132);

    const int tid = threadIdx.x;
    const int bh = blockIdx.z;
    const int q0 = blockIdx.y * 128, n0 = blockIdx.x * 128;
    const float* Qb = g_Q + ((size_t)bh * TQn + q0) * 64;
    const float* Kb = g_K + ((size_t)bh * TKn + n0) * 64;

    {
        const int m = tid & 127, half = tid >> 7;
#pragma unroll
        for (int cc = 0; cc < 8; ++cc) {
            const int d4 = half + 2 * cc;
            float4 qv = *(const float4*)(Qb + (size_t)m * 64 + d4 * 4);
            Qs[d4 * 4 + 0][m] = qv.x * 0.125f;
            Qs[d4 * 4 + 1][m] = qv.y * 0.125f;
            Qs[d4 * 4 + 2][m] = qv.z * 0.125f;
            Qs[d4 * 4 + 3][m] = qv.w * 0.125f;
            float4 kv = *(const float4*)(Kb + (size_t)m * 64 + d4 * 4);
            Ks[d4 * 4 + 0][m] = kv.x;
            Ks[d4 * 4 + 1][m] = kv.y;
            Ks[d4 * 4 + 2][m] = kv.z;
            Ks[d4 * 4 + 3][m] = kv.w;
        }
    }
    __syncthreads();

    const int tx = tid & 15, ty = tid >> 4;
    unsigned long long acc2[8][4];
#pragma unroll
    for (int i = 0; i < 8; ++i)
#pragma unroll
        for (int jp = 0; jp < 4; ++jp) acc2[i][jp] = 0ull;

#pragma unroll 8
    for (int kk = 0; kk < 64; ++kk) {
        float4 a0 = *(const float4*)&Qs[kk][ty * 8];
        float4 a1 = *(const float4*)&Qs[kk][ty * 8 + 4];
        ulonglong2 b01 = *(const ulonglong2*)&Ks[kk][tx * 8];
        ulonglong2 b23 = *(const ulonglong2*)&Ks[kk][tx * 8 + 4];
        unsigned long long b2[4] = {b01.x, b01.y, b23.x, b23.y};
        float ar[8] = {a0.x, a0.y, a0.z, a0.w, a1.x, a1.y, a1.z, a1.w};
#pragma unroll
        for (int i = 0; i < 8; ++i) {
            unsigned long long pa = pack2(ar[i]);
#pragma unroll
            for (int jp = 0; jp < 4; ++jp) FFMA2(acc2[i][jp], pa, b2[jp]);
        }
    }

    const int mode = g_mask_mode, b = bh >> 4;
    unsigned char mku[8];
#pragma unroll
    for (int j = 0; j < 8; ++j) mku[j] = mask_at(mask, mode, b * TKn + n0 + tx * 8 + j);

#pragma unroll
    for (int i = 0; i < 8; ++i) {
        float* Lp = g_L + ((size_t)bh * TQn + q0 + ty * 8 + i) * TKn + n0 + tx * 8;
        float o[8];
#pragma unroll
        for (int jp = 0; jp < 4; ++jp) unpack2(acc2[i][jp], o[2 * jp], o[2 * jp + 1]);
#pragma unroll
        for (int j = 0; j < 8; ++j) if (mku[j]) o[j] = NEG_BIG;
        __stcs((float4*)Lp,       make_float4(o[0], o[1], o[2], o[3]));
        __stcs((float4*)(Lp + 4), make_float4(o[4], o[5], o[6], o[7]));
    }
}

// ---------------------------------------------------------------------------
// Top-64 + softmax + sparse AV (unchanged from round 11)
// ---------------------------------------------------------------------------
__device__ __forceinline__ int cnt_ge(const float (&a)[64], float t)
{
    int c = 0;
#pragma unroll
    for (int j = 0; j < 64; ++j) c += (a[j] >= t) ? 1 : 0;
    return __reduce_add_sync(0xffffffffu, c);
}

__global__ __launch_bounds__(256, 2) void topk_av_k()
{
    __shared__ int   skey[8][80];
    __shared__ float swgt[8][80];

    const int lane = threadIdx.x & 31, w = threadIdx.x >> 5;
    const int b = blockIdx.z, h = blockIdx.y;
    const int bh = b * Hn + h;
    const int q = blockIdx.x * 8 + w;

    const float* Lq = g_L + ((size_t)bh * TQn + q) * TKn;
    float acc[64];
#pragma unroll
    for (int j = 0; j < 64; ++j) acc[j] = __ldcs(Lq + j * 32 + lane);

    float m = NEG_BIG;
#pragma unroll
    for (int j = 0; j < 64; ++j) m = fmaxf(m, acc[j]);
#pragma unroll
    for (int o = 16; o > 0; o >>= 1) m = fmaxf(m, __shfl_xor_sync(0xffffffffu, m, o));

    // bracketing: lo has cnt>=64, hi has cnt<64 (hi=m assumed cnt~1)
    float lo = m - 32.0f, hi = m;
    int clo = cnt_ge(acc, lo), chi = 1;
    int guard = 0;
    while (clo < 64 && guard++ < 90) { lo = m - 2.0f * (m - lo); clo = cnt_ge(acc, lo); }

    for (int it = 0; it < 32 && clo != 64; ++it) {
        float t;
        if (it == 0) {
            t = m - 1.9f;
        } else {
            float f = (__logf(64.f) - __logf((float)chi)) /
                      (__logf((float)clo) - __logf((float)chi));
            t = hi + f * (lo - hi);
        }
        if (!(t > lo && t < hi)) t = 0.5f * (lo + hi);
        if (!(t > lo && t < hi)) break;
        int c2 = cnt_ge(acc, t);
        if (c2 >= 64) { lo = t; clo = c2; } else { hi = t; chi = c2; }
    }
    const float thr = lo;

    int base = 0;
#pragma unroll
    for (int j = 0; j < 64; ++j) {
        bool sel = acc[j] >= thr;
        unsigned bal = __ballot_sync(0xffffffffu, sel);
        if (sel) {
            int pos = base + __popc(bal & ((1u << lane) - 1u));
            if (pos < 80) {
                skey[w][pos] = j * 32 + lane;
                swgt[w][pos] = __expf(acc[j] - m);
            }
        }
        base += __popc(bal);
    }
    const int nsel = base < 80 ? base : 80;
    __syncwarp();

    float z = 0.f;
    for (int i = lane; i < nsel; i += 32) z += swgt[w][i];
#pragma unroll
    for (int o = 16; o > 0; o >>= 1) z += __shfl_xor_sync(0xffffffffu, z, o);

    const float* Vb = g_V + (size_t)bh * TKn * 64;
    float o0 = 0.f, o1 = 0.f;
    int i = 0;
    for (; i + 8 <= nsel; i += 8) {
        int   kv[8]; float wv[8];
#pragma unroll
        for (int u = 0; u < 8; ++u) { kv[u] = skey[w][i + u]; wv[u] = swgt[w][i + u]; }
        float2 vv[8];
#pragma unroll
        for (int u = 0; u < 8; ++u)
            vv[u] = *(const float2*)(Vb + (size_t)kv[u] * 64 + 2 * lane);
#pragma unroll
        for (int u = 0; u < 8; ++u) { o0 += wv[u] * vv[u].x; o1 += wv[u] * vv[u].y; }
    }
    for (; i < nsel; ++i) {
        float wv = swgt[w][i];
        float2 vv = *(const float2*)(Vb + (size_t)skey[w][i] * 64 + 2 * lane);
        o0 += wv * vv.x;
        o1 += wv * vv.y;
    }

    // epilogue: normalized output -> bf16x2 split planes (fused split_A)
    const float inv = 1.0f / z;
    const float r0 = o0 * inv, r1 = o1 * inv;
    __nv_bfloat16 x1 = __float2bfloat16(r0);
    __nv_bfloat16 x2 = __float2bfloat16(r0 - __bfloat162float(x1));
    __nv_bfloat16 y1 = __float2bfloat16(r1);
    __nv_bfloat16 y2 = __float2bfloat16(r1 - __bfloat162float(y1));
    const size_t MK = (size_t)Bb * TQn * DQn;
    const size_t o = ((size_t)(b * TQn + q)) * DQn + h * 64 + 2 * lane;
    *(__nv_bfloat162*)(g_Asp + o)      = __nv_bfloat162(x1, y1);
    *(__nv_bfloat162*)(g_Asp + MK + o) = __nv_bfloat162(x2, y2);
}

// ---------------------------------------------------------------------------
extern "C" void kernel_launch(void* const* d_in, const int* in_sizes, int n_in,
                              void* d_out, int out_size)
{
    const float* x   = (const float*)d_in[0];
    const float* ctx = (const float*)d_in[1];
    const void*  msk = d_in[2];
    const float* Wq = (const float*)d_in[3];
    const float* bq = (const float*)d_in[4];
    const float* Wk = (const float*)d_in[5];
    const float* bk = (const float*)d_in[6];
    const float* Wv = (const float*)d_in[7];
    const float* bv = (const float*)d_in[8];
    const float* Wo = (const float*)d_in[9];
    const float* bo = (const float*)d_in[10];
    float* out = (float*)d_out;

    const int qk_smem = 2 * 64 * 132 * sizeof(float);   // 67.6 KB
    static bool attr_done = false;
    if (!attr_done) {
        cudaFuncSetAttribute(qk_logits_k, cudaFuncAttributeMaxDynamicSharedMemorySize, qk_smem);
        attr_done = true;
    }

    detect_mask_kernel<<<1, 256>>>((const unsigned char*)msk);

    // Q + K projections: one launch, compile-time dual body (384 CTAs)
    qkproj_k<<<384, 256>>>(x, Wq, bq, ctx, Wk, bk);

    // V projection: wmma bf16x2 (selection-independent)
    split_W_k<0><<<dim3(32, 24), dim3(32, 8)>>>(Wv, 768);
    split_W_k<1><<<dim3(32, 32), dim3(32, 8)>>>(Wo, 1024);
    split_A_k<<<4096, 256>>>(ctx, (size_t)4096 * 768);
    wmma_gemm<2><<<dim3(16, 32), 256>>>(bv, nullptr, 4096, 768, 2048);

    // masked logits (bitwise-identical)
    qk_logits_k<<<dim3(TKn / 128, TQn / 128, Bb * Hn), 256, qk_smem>>>(msk);
    // top-64 + softmax + sparse AV (writes bf16 split planes directly)
    topk_av_k<<<dim3(TQn / 8, Hn, Bb), 256>>>();

    // output projection: wmma bf16x2 (reads planes written by topk_av_k)
    wmma_gemm<4><<<dim3(16, 16), 256>>>(bo, out, 2048, 1024, 1024);
}

// round 14
// speedup vs baseline: 1.0488x; 1.0312x over previous
#include <cuda_runtime.h>
#include <cuda_bf16.h>
#include <mma.h>
#include <math.h>
#include <float.h>

using namespace nvcuda;

#define NEG_BIG (-3.402823466e38f)

constexpr int Bb = 2, TQn = 1024, TKn = 2048, DQn = 1024, DCn = 768, Hn = 16, DHn = 64;

// Scratch (allocation-free rule: __device__ globals), referenced only in device code.
__device__ float g_Q[Bb * Hn * TQn * DHn];          // (b,h,q,d)   8 MB
__device__ float g_K[Bb * Hn * TKn * DHn];          // (b,h,k,d)  16 MB
__device__ float g_V[Bb * Hn * TKn * DHn];          // (b,h,k,d)  16 MB
__device__ float g_L[(size_t)Bb * Hn * TQn * TKn];  // logits 256 MB
__device__ int   g_mask_mode;
// bf16x2 split planes (V / out projections only — selection-independent)
__device__ __nv_bfloat16 g_Asp[2ull * 4096 * 1024];     // activation splits
__device__ __nv_bfloat16 g_Ws[2][2ull * 1024 * 1024];   // transposed weight splits [n][k]: 0=Wv, 1=Wo

// ---------------- packed f32x2 helpers ----------------
__device__ __forceinline__ unsigned long long pack2(float x) {
    unsigned long long r; asm("mov.b64 %0, {%1, %1};" : "=l"(r) : "f"(x)); return r;
}
#define FFMA2(acc, a, b) asm("fma.rn.f32x2 %0, %1, %2, %0;" : "+l"(acc) : "l"(a), "l"(b))
__device__ __forceinline__ void unpack2(unsigned long long v, float& lo, float& hi) {
    asm("mov.b64 {%0, %1}, %2;" : "=f"(lo), "=f"(hi) : "l"(v));
}

// ---------------------------------------------------------------------------
// Mask dtype detection
// ---------------------------------------------------------------------------
__global__ void detect_mask_kernel(const unsigned char* __restrict__ m)
{
    __shared__ int s_big, s_mis;
    if (threadIdx.x == 0) { s_big = 0; s_mis = 0; }
    __syncthreads();
    int big = 0, mis = 0;
    for (int i = threadIdx.x; i < Bb * TKn; i += 256) {
        unsigned char v = m[i];
        if (v > 1) big = 1;
        else if (v == 1 && (i & 3)) mis = 1;
    }
    if (big) atomicOr(&s_big, 1);
    if (mis) atomicOr(&s_mis, 1);
    __syncthreads();
    if (threadIdx.x == 0) g_mask_mode = s_big ? 2 : (s_mis ? 0 : 1);
}

__device__ __forceinline__ unsigned char mask_at(const void* mask, int mode, int idx)
{
    if (mode == 2) return ((const float*)mask)[idx] != 0.f;
    if (mode == 1) return ((const int*)mask)[idx] != 0;
    return ((const unsigned char*)mask)[idx];
}

// ---------------------------------------------------------------------------
// Q projection: 128m x 64n tiles (256 CTAs -> full single wave).
// Per-element accumulation chains bitwise-identical to the 128x128 version:
// same k-order (BK=8 chunks, kk ascending), same FFMA2 (even,odd) column
// pairing (tx*4 is even), same epilogue formula.
// ---------------------------------------------------------------------------
__global__ __launch_bounds__(256, 2) void qproj_k(
    const float* __restrict__ A, const float* __restrict__ W,
    const float* __restrict__ bias)
{
    __shared__ float As[2][8][128];
    __shared__ float Bs[2][8][68];            // 68*4B=272B row stride (16B-multiple)
    const int tid = threadIdx.x;
    const int tx = tid & 15, ty = tid >> 4;   // 16 col-groups x 4, 16 row-groups x 8
    const int m0 = blockIdx.y * 128, n0 = blockIdx.x * 64;
    const int K = 1024, N = 1024, T = TQn;

    unsigned long long acc2[8][2];
#pragma unroll
    for (int i = 0; i < 8; ++i) { acc2[i][0] = 0ull; acc2[i][1] = 0ull; }

    const int arow = tid >> 1, acol = (tid & 1) * 4;
    const int brow = tid >> 5, bcol = (tid & 31) * 2;
    const float* Ap = A + (size_t)(m0 + arow) * K + acol;
    const float* Wp = W + (size_t)brow * N + n0 + bcol;

    {
        float4 av = *(const float4*)(Ap);
        float2 bv = *(const float2*)(Wp);
        As[0][acol + 0][arow] = av.x;
        As[0][acol + 1][arow] = av.y;
        As[0][acol + 2][arow] = av.z;
        As[0][acol + 3][arow] = av.w;
        *(float2*)&Bs[0][brow][bcol] = bv;
    }
    __syncthreads();

    int buf = 0;
    for (int k0 = 0; k0 < K; k0 += 8) {
        float4 av; float2 bv;
        const bool has_next = (k0 + 8) < K;
        if (has_next) {
            av = *(const float4*)(Ap + k0 + 8);
            bv = *(const float2*)(Wp + (size_t)(k0 + 8) * N);
        }
#pragma unroll
        for (int kk = 0; kk < 8; ++kk) {
            float4 a0 = *(const float4*)&As[buf][kk][ty * 8];
            float4 a1 = *(const float4*)&As[buf][kk][ty * 8 + 4];
            ulonglong2 bpair = *(const ulonglong2*)&Bs[buf][kk][tx * 4];
            float ar[8] = {a0.x, a0.y, a0.z, a0.w, a1.x, a1.y, a1.z, a1.w};
#pragma unroll
            for (int i = 0; i < 8; ++i) {
                unsigned long long pa = pack2(ar[i]);
                FFMA2(acc2[i][0], pa, bpair.x);
                FFMA2(acc2[i][1], pa, bpair.y);
            }
        }
        if (has_next) {
            const int nb = buf ^ 1;
            As[nb][acol + 0][arow] = av.x;
            As[nb][acol + 1][arow] = av.y;
            As[nb][acol + 2][arow] = av.z;
            As[nb][acol + 3][arow] = av.w;
            *(float2*)&Bs[nb][brow][bcol] = bv;
            __syncthreads();
            buf = nb;
        }
    }

#pragma unroll
    for (int i = 0; i < 8; ++i) {
        int r = m0 + ty * 8 + i;
        float accf[4];
        unpack2(acc2[i][0], accf[0], accf[1]);
        unpack2(acc2[i][1], accf[2], accf[3]);
#pragma unroll
        for (int j = 0; j < 4; ++j) {
            int c = n0 + tx * 4 + j;
            float v = accf[j] + bias[c];
            int bb = r / T, tl = r - bb * T;
            int h = c >> 6, d = c & 63;
            g_Q[((size_t)((bb * Hn + h) * T + tl) << 6) + d] = v;
        }
    }
}

// ---------------------------------------------------------------------------
// fp32 SGEMM (round-6 proven): K projection. BM=BN=128, BK=8, 256 thr,
// 8x8 micro, double-buffered, packed f32x2 (bitwise == scalar fp32 chains).
// ---------------------------------------------------------------------------
__global__ __launch_bounds__(256, 2) void kproj_k(
    const float* __restrict__ A, const float* __restrict__ W,
    const float* __restrict__ bias)
{
    __shared__ float As[2][8][128];
    __shared__ float Bs[2][8][132];
    const int tid = threadIdx.x;
    const int tx = tid & 15, ty = tid >> 4;
    const int m0 = blockIdx.y * 128, n0 = blockIdx.x * 128;
    const int K = 768, N = 1024, T = TKn;

    unsigned long long acc2[8][4];
#pragma unroll
    for (int i = 0; i < 8; ++i)
#pragma unroll
        for (int jp = 0; jp < 4; ++jp) acc2[i][jp] = 0ull;

    const int arow = tid >> 1, acol = (tid & 1) * 4;
    const int brow = tid >> 5, bcol = (tid & 31) * 4;
    const float* Ap = A + (size_t)(m0 + arow) * K + acol;
    const float* Wp = W + (size_t)brow * N + n0 + bcol;

    {
        float4 av = *(const float4*)(Ap);
        float4 bv = *(const float4*)(Wp);
        As[0][acol + 0][arow] = av.x;
        As[0][acol + 1][arow] = av.y;
        As[0][acol + 2][arow] = av.z;
        As[0][acol + 3][arow] = av.w;
        *(float4*)&Bs[0][brow][bcol] = bv;
    }
    __syncthreads();

    int buf = 0;
    for (int k0 = 0; k0 < K; k0 += 8) {
        float4 av, bv;
        const bool has_next = (k0 + 8) < K;
        if (has_next) {
            av = *(const float4*)(Ap + k0 + 8);
            bv = *(const float4*)(Wp + (size_t)(k0 + 8) * N);
        }
#pragma unroll
        for (int kk = 0; kk < 8; ++kk) {
            float4 a0 = *(const float4*)&As[buf][kk][ty * 8];
            float4 a1 = *(const float4*)&As[buf][kk][ty * 8 + 4];
            ulonglong2 b01 = *(const ulonglong2*)&Bs[buf][kk][tx * 8];
            ulonglong2 b23 = *(const ulonglong2*)&Bs[buf][kk][tx * 8 + 4];
            unsigned long long b2[4] = {b01.x, b01.y, b23.x, b23.y};
            float ar[8] = {a0.x, a0.y, a0.z, a0.w, a1.x, a1.y, a1.z, a1.w};
#pragma unroll
            for (int i = 0; i < 8; ++i) {
                unsigned long long pa = pack2(ar[i]);
#pragma unroll
                for (int jp = 0; jp < 4; ++jp) FFMA2(acc2[i][jp], pa, b2[jp]);
            }
        }
        if (has_next) {
            const int nb = buf ^ 1;
            As[nb][acol + 0][arow] = av.x;
            As[nb][acol + 1][arow] = av.y;
            As[nb][acol + 2][arow] = av.z;
            As[nb][acol + 3][arow] = av.w;
            *(float4*)&Bs[nb][brow][bcol] = bv;
            __syncthreads();
            buf = nb;
        }
    }

#pragma unroll
    for (int i = 0; i < 8; ++i) {
        int r = m0 + ty * 8 + i;
        float accf[8];
#pragma unroll
        for (int jp = 0; jp < 4; ++jp) unpack2(acc2[i][jp], accf[2 * jp], accf[2 * jp + 1]);
#pragma unroll
        for (int j = 0; j < 8; ++j) {
            int c = n0 + tx * 8 + j;
            float v = accf[j] + bias[c];
            int bb = r / T, tl = r - bb * T;
            int h = c >> 6, d = c & 63;
            g_K[((size_t)((bb * Hn + h) * T + tl) << 6) + d] = v;
        }
    }
}

// ---------------------------------------------------------------------------
// bf16x2 split of ctx activations: A -> 2 bf16 planes in g_Asp (stride MK).
// ---------------------------------------------------------------------------
__global__ void split_A_k(const float* __restrict__ A, size_t MK)
{
    for (size_t i = ((size_t)blockIdx.x * 256 + threadIdx.x) * 2; i < MK;
         i += (size_t)gridDim.x * 512) {
        float2 f = *(const float2*)(A + i);
        __nv_bfloat16 ax1 = __float2bfloat16(f.x);
        __nv_bfloat16 ax2 = __float2bfloat16(f.x - __bfloat162float(ax1));
        __nv_bfloat16 ay1 = __float2bfloat16(f.y);
        __nv_bfloat16 ay2 = __float2bfloat16(f.y - __bfloat162float(ay1));
        *(__nv_bfloat162*)(g_Asp + i)      = __nv_bfloat162(ax1, ay1);
        *(__nv_bfloat162*)(g_Asp + MK + i) = __nv_bfloat162(ax2, ay2);
    }
}

// ---------------------------------------------------------------------------
// W split + transpose: W[K][1024] f32 -> g_Ws[WIDX] 2 bf16 planes [1024][K].
// ---------------------------------------------------------------------------
template <int WIDX>
__global__ void split_W_k(const float* __restrict__ W, int K)
{
    __shared__ float t[32][33];
    const int k0 = blockIdx.y * 32, n0 = blockIdx.x * 32;
    const int tx = threadIdx.x, ty = threadIdx.y;   // (32, 8)
#pragma unroll
    for (int i = 0; i < 4; ++i)
        t[ty + 8 * i][tx] = W[(size_t)(k0 + ty + 8 * i) * 1024 + n0 + tx];
    __syncthreads();
    __nv_bfloat16* P = g_Ws[WIDX];
    const size_t NK = (size_t)1024 * K;
#pragma unroll
    for (int i = 0; i < 4; ++i) {
        int n = ty + 8 * i;
        float f = t[tx][n];                          // = W[k0+tx][n0+n]
        __nv_bfloat16 b1 = __float2bfloat16(f);
        __nv_bfloat16 b2 = __float2bfloat16(f - __bfloat162float(b1));
        size_t o = (size_t)(n0 + n) * K + k0 + tx;
        P[o] = b1; P[NK + o] = b2;
    }
}

// ---------------------------------------------------------------------------
// wmma bf16x2 GEMM: C[M,1024] = A @ W + bias via 3 split products
// (A1B1 + A1B2 + A2B1) folded into one extended-K loop. Tile 128m x 64n x 32k,
// 8 warps (4m x 2n), HMMA m16n16k16 bf16->f32, double-buffered smem.
// DST 2: head-scatter to g_V; DST 4: plain out.
// ---------------------------------------------------------------------------
template <int DST>
__global__ __launch_bounds__(256, 2) void wmma_gemm(
    const float* __restrict__ bias, float* __restrict__ Cext, int M, int K, int T)
{
    __shared__ __align__(16) unsigned char smraw[30720];
    __shared__ float sbias[64];

    const int tid = threadIdx.x, wid = tid >> 5;
    const int wm = wid & 3, wn = wid >> 2;
    const int n0 = blockIdx.x * 64, m0 = blockIdx.y * 128;

    auto Arow = [&](int buf, int r) -> __nv_bfloat16* {
        return (__nv_bfloat16*)(smraw + buf * 10240 + r * 80);
    };
    auto Brow = [&](int buf, int r) -> __nv_bfloat16* {
        return (__nv_bfloat16*)(smraw + 20480 + buf * 5120 + r * 80);
    };

    if (tid < 64) sbias[tid] = bias[n0 + tid];

    const int WIDX = (DST == 2) ? 0 : 1;
    const __nv_bfloat16* Wt = g_Ws[WIDX];
    const size_t MK = (size_t)M * K, NK = (size_t)1024 * K;
    const int kch = K >> 5, nch = 3 * kch;
    const int PA[3] = {0, 0, 1};
    const int PB[3] = {0, 1, 0};

    wmma::fragment<wmma::accumulator, 16, 16, 16, float> acc[2][2];
#pragma unroll
    for (int i = 0; i < 2; ++i)
#pragma unroll
        for (int j = 0; j < 2; ++j) wmma::fill_fragment(acc[i][j], 0.f);

    {
        const __nv_bfloat16* gA = g_Asp + (size_t)m0 * K;
        const __nv_bfloat16* gB = Wt + (size_t)n0 * K;
#pragma unroll
        for (int u = 0; u < 2; ++u) {
            int idx = u * 256 + tid, row = idx >> 2, c8 = idx & 3;
            uint4 v = *(const uint4*)(gA + (size_t)row * K + c8 * 8);
            *(uint4*)(Arow(0, row) + c8 * 8) = v;
        }
        {
            int row = tid >> 2, c8 = tid & 3;
            uint4 v = *(const uint4*)(gB + (size_t)row * K + c8 * 8);
            *(uint4*)(Brow(0, row) + c8 * 8) = v;
        }
    }
    __syncthreads();

    int buf = 0;
    for (int c = 0; c < nch; ++c) {
        uint4 va0, va1, vb;
        const bool has_next = (c + 1) < nch;
        if (has_next) {
            const int cn = c + 1, sub = cn / kch, ko = (cn - sub * kch) << 5;
            const __nv_bfloat16* gA = g_Asp + (size_t)PA[sub] * MK + (size_t)m0 * K + ko;
            const __nv_bfloat16* gB = Wt + (size_t)PB[sub] * NK + (size_t)n0 * K + ko;
            {
                int i0 = tid, r = i0 >> 2, c8 = i0 & 3;
                va0 = *(const uint4*)(gA + (size_t)r * K + c8 * 8);
            }
            {
                int i1 = 256 + tid, r = i1 >> 2, c8 = i1 & 3;
                va1 = *(const uint4*)(gA + (size_t)r * K + c8 * 8);
            }
            {
                int r = tid >> 2, c8 = tid & 3;
                vb = *(const uint4*)(gB + (size_t)r * K + c8 * 8);
            }
        }

#pragma unroll
        for (int ks = 0; ks < 2; ++ks) {
            wmma::fragment<wmma::matrix_a, 16, 16, 16, __nv_bfloat16, wmma::row_major> af[2];
            wmma::fragment<wmma::matrix_b, 16, 16, 16, __nv_bfloat16, wmma::col_major> bf[2];
#pragma unroll
            for (int mi = 0; mi < 2; ++mi)
                wmma::load_matrix_sync(af[mi], Arow(buf, wm * 32 + mi * 16) + ks * 16, 40);
#pragma unroll
            for (int ni = 0; ni < 2; ++ni)
                wmma::load_matrix_sync(bf[ni], Brow(buf, wn * 32 + ni * 16) + ks * 16, 40);
#pragma unroll
            for (int mi = 0; mi < 2; ++mi)
#pragma unroll
                for (int ni = 0; ni < 2; ++ni)
                    wmma::mma_sync(acc[mi][ni], af[mi], bf[ni], acc[mi][ni]);
        }

        if (has_next) {
            const int nb = buf ^ 1;
            {
                int i0 = tid, r = i0 >> 2, c8 = i0 & 3;
                *(uint4*)(Arow(nb, r) + c8 * 8) = va0;
            }
            {
                int i1 = 256 + tid, r = i1 >> 2, c8 = i1 & 3;
                *(uint4*)(Arow(nb, r) + c8 * 8) = va1;
            }
            {
                int r = tid >> 2, c8 = tid & 3;
                *(uint4*)(Brow(nb, r) + c8 * 8) = vb;
            }
            __syncthreads();
            buf = nb;
        }
    }

    float (*Cs)[36] = (float (*)[36])smraw;
    const int r = tid >> 1, hc = (tid & 1) * 16;
    const int m = m0 + r;
    float* dst;
    if (DST == 2) {
        int bb = m / T, tl = m - bb * T, h = n0 >> 6;
        dst = g_V + ((size_t)((bb * Hn + h) * T + tl) << 6);
    } else {
        dst = Cext + (size_t)m * 1024 + n0;
    }

#pragma unroll
    for (int p = 0; p < 2; ++p) {
        __syncthreads();
        if (wn == p) {
#pragma unroll
            for (int mi = 0; mi < 2; ++mi)
#pragma unroll
                for (int ni = 0; ni < 2; ++ni)
                    wmma::store_matrix_sync(&Cs[wm * 32 + mi * 16][ni * 16],
                                            acc[mi][ni], 36, wmma::mem_row_major);
        }
        __syncthreads();
#pragma unroll
        for (int j4 = 0; j4 < 4; ++j4) {
            int cc = hc + j4 * 4;
            float4 v;
            v.x = Cs[r][cc + 0] + sbias[p * 32 + cc + 0];
            v.y = Cs[r][cc + 1] + sbias[p * 32 + cc + 1];
            v.z = Cs[r][cc + 2] + sbias[p * 32 + cc + 2];
            v.w = Cs[r][cc + 3] + sbias[p * 32 + cc + 3];
            *(float4*)(dst + p * 32 + cc) = v;
        }
    }
}

// ---------------------------------------------------------------------------
// QK^T logits GEMM (bitwise-identical to rounds 4-13)
// ---------------------------------------------------------------------------
__global__ __launch_bounds__(256, 2) void qk_logits_k(const void* __restrict__ mask)
{
    extern __shared__ float sm[];
    float (*Qs)[132] = (float (*)[132])sm;
    float (*Ks)[132] = (float (*)[132])(sm + 64 * 132);

    const int tid = threadIdx.x;
    const int bh = blockIdx.z;
    const int q0 = blockIdx.y * 128, n0 = blockIdx.x * 128;
    const float* Qb = g_Q + ((size_t)bh * TQn + q0) * 64;
    const float* Kb = g_K + ((size_t)bh * TKn + n0) * 64;

    {
        const int m = tid & 127, half = tid >> 7;
#pragma unroll
        for (int cc = 0; cc < 8; ++cc) {
            const int d4 = half + 2 * cc;
            float4 qv = *(const float4*)(Qb + (size_t)m * 64 + d4 * 4);
            Qs[d4 * 4 + 0][m] = qv.x * 0.125f;
            Qs[d4 * 4 + 1][m] = qv.y * 0.125f;
            Qs[d4 * 4 + 2][m] = qv.z * 0.125f;
            Qs[d4 * 4 + 3][m] = qv.w * 0.125f;
            float4 kv = *(const float4*)(Kb + (size_t)m * 64 + d4 * 4);
            Ks[d4 * 4 + 0][m] = kv.x;
            Ks[d4 * 4 + 1][m] = kv.y;
            Ks[d4 * 4 + 2][m] = kv.z;
            Ks[d4 * 4 + 3][m] = kv.w;
        }
    }
    __syncthreads();

    const int tx = tid & 15, ty = tid >> 4;
    unsigned long long acc2[8][4];
#pragma unroll
    for (int i = 0; i < 8; ++i)
#pragma unroll
        for (int jp = 0; jp < 4; ++jp) acc2[i][jp] = 0ull;

#pragma unroll 8
    for (int kk = 0; kk < 64; ++kk) {
        float4 a0 = *(const float4*)&Qs[kk][ty * 8];
        float4 a1 = *(const float4*)&Qs[kk][ty * 8 + 4];
        ulonglong2 b01 = *(const ulonglong2*)&Ks[kk][tx * 8];
        ulonglong2 b23 = *(const ulonglong2*)&Ks[kk][tx * 8 + 4];
        unsigned long long b2[4] = {b01.x, b01.y, b23.x, b23.y};
        float ar[8] = {a0.x, a0.y, a0.z, a0.w, a1.x, a1.y, a1.z, a1.w};
#pragma unroll
        for (int i = 0; i < 8; ++i) {
            unsigned long long pa = pack2(ar[i]);
#pragma unroll
            for (int jp = 0; jp < 4; ++jp) FFMA2(acc2[i][jp], pa, b2[jp]);
        }
    }

    const int mode = g_mask_mode, b = bh >> 4;
    unsigned char mku[8];
#pragma unroll
    for (int j = 0; j < 8; ++j) mku[j] = mask_at(mask, mode, b * TKn + n0 + tx * 8 + j);

#pragma unroll
    for (int i = 0; i < 8; ++i) {
        float* Lp = g_L + ((size_t)bh * TQn + q0 + ty * 8 + i) * TKn + n0 + tx * 8;
        float o[8];
#pragma unroll
        for (int jp = 0; jp < 4; ++jp) unpack2(acc2[i][jp], o[2 * jp], o[2 * jp + 1]);
#pragma unroll
        for (int j = 0; j < 8; ++j) if (mku[j]) o[j] = NEG_BIG;
        __stcs((float4*)Lp,       make_float4(o[0], o[1], o[2], o[3]));
        __stcs((float4*)(Lp + 4), make_float4(o[4], o[5], o[6], o[7]));
    }
}

// ---------------------------------------------------------------------------
// Top-64 + softmax + sparse AV (unchanged from round 11)
// ---------------------------------------------------------------------------
__device__ __forceinline__ int cnt_ge(const float (&a)[64], float t)
{
    int c = 0;
#pragma unroll
    for (int j = 0; j < 64; ++j) c += (a[j] >= t) ? 1 : 0;
    return __reduce_add_sync(0xffffffffu, c);
}

__global__ __launch_bounds__(256, 2) void topk_av_k()
{
    __shared__ int   skey[8][80];
    __shared__ float swgt[8][80];

    const int lane = threadIdx.x & 31, w = threadIdx.x >> 5;
    const int b = blockIdx.z, h = blockIdx.y;
    const int bh = b * Hn + h;
    const int q = blockIdx.x * 8 + w;

    const float* Lq = g_L + ((size_t)bh * TQn + q) * TKn;
    float acc[64];
#pragma unroll
    for (int j = 0; j < 64; ++j) acc[j] = __ldcs(Lq + j * 32 + lane);

    float m = NEG_BIG;
#pragma unroll
    for (int j = 0; j < 64; ++j) m = fmaxf(m, acc[j]);
#pragma unroll
    for (int o = 16; o > 0; o >>= 1) m = fmaxf(m, __shfl_xor_sync(0xffffffffu, m, o));

    float lo = m - 32.0f, hi = m;
    int clo = cnt_ge(acc, lo), chi = 1;
    int guard = 0;
    while (clo < 64 && guard++ < 90) { lo = m - 2.0f * (m - lo); clo = cnt_ge(acc, lo); }

    for (int it = 0; it < 32 && clo != 64; ++it) {
        float t;
        if (it == 0) {
            t = m - 1.9f;
        } else {
            float f = (__logf(64.f) - __logf((float)chi)) /
                      (__logf((float)clo) - __logf((float)chi));
            t = hi + f * (lo - hi);
        }
        if (!(t > lo && t < hi)) t = 0.5f * (lo + hi);
        if (!(t > lo && t < hi)) break;
        int c2 = cnt_ge(acc, t);
        if (c2 >= 64) { lo = t; clo = c2; } else { hi = t; chi = c2; }
    }
    const float thr = lo;

    int base = 0;
#pragma unroll
    for (int j = 0; j < 64; ++j) {
        bool sel = acc[j] >= thr;
        unsigned bal = __ballot_sync(0xffffffffu, sel);
        if (sel) {
            int pos = base + __popc(bal & ((1u << lane) - 1u));
            if (pos < 80) {
                skey[w][pos] = j * 32 + lane;
                swgt[w][pos] = __expf(acc[j] - m);
            }
        }
        base += __popc(bal);
    }
    const int nsel = base < 80 ? base : 80;
    __syncwarp();

    float z = 0.f;
    for (int i = lane; i < nsel; i += 32) z += swgt[w][i];
#pragma unroll
    for (int o = 16; o > 0; o >>= 1) z += __shfl_xor_sync(0xffffffffu, z, o);

    const float* Vb = g_V + (size_t)bh * TKn * 64;
    float o0 = 0.f, o1 = 0.f;
    int i = 0;
    for (; i + 8 <= nsel; i += 8) {
        int   kv[8]; float wv[8];
#pragma unroll
        for (int u = 0; u < 8; ++u) { kv[u] = skey[w][i + u]; wv[u] = swgt[w][i + u]; }
        float2 vv[8];
#pragma unroll
        for (int u = 0; u < 8; ++u)
            vv[u] = *(const float2*)(Vb + (size_t)kv[u] * 64 + 2 * lane);
#pragma unroll
        for (int u = 0; u < 8; ++u) { o0 += wv[u] * vv[u].x; o1 += wv[u] * vv[u].y; }
    }
    for (; i < nsel; ++i) {
        float wv = swgt[w][i];
        float2 vv = *(const float2*)(Vb + (size_t)skey[w][i] * 64 + 2 * lane);
        o0 += wv * vv.x;
        o1 += wv * vv.y;
    }

    const float inv = 1.0f / z;
    const float r0 = o0 * inv, r1 = o1 * inv;
    __nv_bfloat16 x1 = __float2bfloat16(r0);
    __nv_bfloat16 x2 = __float2bfloat16(r0 - __bfloat162float(x1));
    __nv_bfloat16 y1 = __float2bfloat16(r1);
    __nv_bfloat16 y2 = __float2bfloat16(r1 - __bfloat162float(y1));
    const size_t MK = (size_t)Bb * TQn * DQn;
    const size_t o = ((size_t)(b * TQn + q)) * DQn + h * 64 + 2 * lane;
    *(__nv_bfloat162*)(g_Asp + o)      = __nv_bfloat162(x1, y1);
    *(__nv_bfloat162*)(g_Asp + MK + o) = __nv_bfloat162(x2, y2);
}

// ---------------------------------------------------------------------------
extern "C" void kernel_launch(void* const* d_in, const int* in_sizes, int n_in,
                              void* d_out, int out_size)
{
    const float* x   = (const float*)d_in[0];
    const float* ctx = (const float*)d_in[1];
    const void*  msk = d_in[2];
    const float* Wq = (const float*)d_in[3];
    const float* bq = (const float*)d_in[4];
    const float* Wk = (const float*)d_in[5];
    const float* bk = (const float*)d_in[6];
    const float* Wv = (const float*)d_in[7];
    const float* bv = (const float*)d_in[8];
    const float* Wo = (const float*)d_in[9];
    const float* bo = (const float*)d_in[10];
    float* out = (float*)d_out;

    const int qk_smem = 2 * 64 * 132 * sizeof(float);   // 67.6 KB
    static bool attr_done = false;
    if (!attr_done) {
        cudaFuncSetAttribute(qk_logits_k, cudaFuncAttributeMaxDynamicSharedMemorySize, qk_smem);
        attr_done = true;
    }

    detect_mask_kernel<<<1, 256>>>((const unsigned char*)msk);

    // Q projection: 128x64 tiles -> 256 CTAs (full wave)
    qproj_k<<<dim3(16, 16), 256>>>(x, Wq, bq);
    // K projection: proven 128x128 path (256 CTAs)
    kproj_k<<<dim3(8, 32), 256>>>(ctx, Wk, bk);

    // V projection: wmma bf16x2 (selection-independent)
    split_W_k<0><<<dim3(32, 24), dim3(32, 8)>>>(Wv, 768);
    split_W_k<1><<<dim3(32, 32), dim3(32, 8)>>>(Wo, 1024);
    split_A_k<<<4096, 256>>>(ctx, (size_t)4096 * 768);
    wmma_gemm<2><<<dim3(16, 32), 256>>>(bv, nullptr, 4096, 768, 2048);

    // masked logits (bitwise-identical)
    qk_logits_k<<<dim3(TKn / 128, TQn / 128, Bb * Hn), 256, qk_smem>>>(msk);
    // top-64 + softmax + sparse AV (writes bf16 split planes directly)
    topk_av_k<<<dim3(TQn / 8, Hn, Bb), 256>>>();

    // output projection: wmma bf16x2 (reads planes written by topk_av_k)
    wmma_gemm<4><<<dim3(16, 16), 256>>>(bo, out, 2048, 1024, 1024);
}

// round 15
// speedup vs baseline: 1.1397x; 1.0867x over previous
#include <cuda_runtime.h>
#include <cuda_bf16.h>
#include <mma.h>
#include <math.h>
#include <float.h>

using namespace nvcuda;

#define NEG_BIG (-3.402823466e38f)

constexpr int Bb = 2, TQn = 1024, TKn = 2048, DQn = 1024, DCn = 768, Hn = 16, DHn = 64;

// Scratch (allocation-free rule: __device__ globals), referenced only in device code.
__device__ float g_Q[Bb * Hn * TQn * DHn];          // (b,h,q,d)   8 MB
__device__ float g_K[Bb * Hn * TKn * DHn];          // (b,h,k,d)  16 MB
__device__ float g_V[Bb * Hn * TKn * DHn];          // (b,h,k,d)  16 MB
__device__ float g_L[(size_t)Bb * Hn * TQn * TKn];  // logits 256 MB
__device__ int   g_mask_mode;
// bf16x2 split planes (V / out projections only — selection-independent)
__device__ __nv_bfloat16 g_Asp[2ull * 4096 * 1024];     // activation splits
__device__ __nv_bfloat16 g_Ws[2][2ull * 1024 * 1024];   // transposed weight splits [n][k]: 0=Wv, 1=Wo

// ---------------- packed f32x2 helpers ----------------
__device__ __forceinline__ unsigned long long pack2(float x) {
    unsigned long long r; asm("mov.b64 %0, {%1, %1};" : "=l"(r) : "f"(x)); return r;
}
#define FFMA2(acc, a, b) asm("fma.rn.f32x2 %0, %1, %2, %0;" : "+l"(acc) : "l"(a), "l"(b))
__device__ __forceinline__ void unpack2(unsigned long long v, float& lo, float& hi) {
    asm("mov.b64 {%0, %1}, %2;" : "=f"(lo), "=f"(hi) : "l"(v));
}

// ---------------------------------------------------------------------------
// Mask dtype detection
// ---------------------------------------------------------------------------
__global__ void detect_mask_kernel(const unsigned char* __restrict__ m)
{
    __shared__ int s_big, s_mis;
    if (threadIdx.x == 0) { s_big = 0; s_mis = 0; }
    __syncthreads();
    int big = 0, mis = 0;
    for (int i = threadIdx.x; i < Bb * TKn; i += 256) {
        unsigned char v = m[i];
        if (v > 1) big = 1;
        else if (v == 1 && (i & 3)) mis = 1;
    }
    if (big) atomicOr(&s_big, 1);
    if (mis) atomicOr(&s_mis, 1);
    __syncthreads();
    if (threadIdx.x == 0) g_mask_mode = s_big ? 2 : (s_mis ? 0 : 1);
}

__device__ __forceinline__ unsigned char mask_at(const void* mask, int mode, int idx)
{
    if (mode == 2) return ((const float*)mask)[idx] != 0.f;
    if (mode == 1) return ((const int*)mask)[idx] != 0;
    return ((const unsigned char*)mask)[idx];
}

// ---------------------------------------------------------------------------
// Q projection: 128m x 64n tiles (256 CTAs). Chains bitwise-identical to the
// 128x128 version (same k-order, FFMA2 even/odd column pairing, epilogue).
// ---------------------------------------------------------------------------
__global__ __launch_bounds__(256, 2) void qproj_k(
    const float* __restrict__ A, const float* __restrict__ W,
    const float* __restrict__ bias)
{
    __shared__ float As[2][8][128];
    __shared__ float Bs[2][8][68];
    const int tid = threadIdx.x;
    const int tx = tid & 15, ty = tid >> 4;
    const int m0 = blockIdx.y * 128, n0 = blockIdx.x * 64;
    const int K = 1024, N = 1024, T = TQn;

    unsigned long long acc2[8][2];
#pragma unroll
    for (int i = 0; i < 8; ++i) { acc2[i][0] = 0ull; acc2[i][1] = 0ull; }

    const int arow = tid >> 1, acol = (tid & 1) * 4;
    const int brow = tid >> 5, bcol = (tid & 31) * 2;
    const float* Ap = A + (size_t)(m0 + arow) * K + acol;
    const float* Wp = W + (size_t)brow * N + n0 + bcol;

    {
        float4 av = *(const float4*)(Ap);
        float2 bv = *(const float2*)(Wp);
        As[0][acol + 0][arow] = av.x;
        As[0][acol + 1][arow] = av.y;
        As[0][acol + 2][arow] = av.z;
        As[0][acol + 3][arow] = av.w;
        *(float2*)&Bs[0][brow][bcol] = bv;
    }
    __syncthreads();

    int buf = 0;
    for (int k0 = 0; k0 < K; k0 += 8) {
        float4 av; float2 bv;
        const bool has_next = (k0 + 8) < K;
        if (has_next) {
            av = *(const float4*)(Ap + k0 + 8);
            bv = *(const float2*)(Wp + (size_t)(k0 + 8) * N);
        }
#pragma unroll
        for (int kk = 0; kk < 8; ++kk) {
            float4 a0 = *(const float4*)&As[buf][kk][ty * 8];
            float4 a1 = *(const float4*)&As[buf][kk][ty * 8 + 4];
            ulonglong2 bpair = *(const ulonglong2*)&Bs[buf][kk][tx * 4];
            float ar[8] = {a0.x, a0.y, a0.z, a0.w, a1.x, a1.y, a1.z, a1.w};
#pragma unroll
            for (int i = 0; i < 8; ++i) {
                unsigned long long pa = pack2(ar[i]);
                FFMA2(acc2[i][0], pa, bpair.x);
                FFMA2(acc2[i][1], pa, bpair.y);
            }
        }
        if (has_next) {
            const int nb = buf ^ 1;
            As[nb][acol + 0][arow] = av.x;
            As[nb][acol + 1][arow] = av.y;
            As[nb][acol + 2][arow] = av.z;
            As[nb][acol + 3][arow] = av.w;
            *(float2*)&Bs[nb][brow][bcol] = bv;
            __syncthreads();
            buf = nb;
        }
    }

#pragma unroll
    for (int i = 0; i < 8; ++i) {
        int r = m0 + ty * 8 + i;
        float accf[4];
        unpack2(acc2[i][0], accf[0], accf[1]);
        unpack2(acc2[i][1], accf[2], accf[3]);
#pragma unroll
        for (int j = 0; j < 4; ++j) {
            int c = n0 + tx * 4 + j;
            float v = accf[j] + bias[c];
            int bb = r / T, tl = r - bb * T;
            int h = c >> 6, d = c & 63;
            g_Q[((size_t)((bb * Hn + h) * T + tl) << 6) + d] = v;
        }
    }
}

// ---------------------------------------------------------------------------
// K projection (round-6 proven 128x128 path).
// ---------------------------------------------------------------------------
__global__ __launch_bounds__(256, 2) void kproj_k(
    const float* __restrict__ A, const float* __restrict__ W,
    const float* __restrict__ bias)
{
    __shared__ float As[2][8][128];
    __shared__ float Bs[2][8][132];
    const int tid = threadIdx.x;
    const int tx = tid & 15, ty = tid >> 4;
    const int m0 = blockIdx.y * 128, n0 = blockIdx.x * 128;
    const int K = 768, N = 1024, T = TKn;

    unsigned long long acc2[8][4];
#pragma unroll
    for (int i = 0; i < 8; ++i)
#pragma unroll
        for (int jp = 0; jp < 4; ++jp) acc2[i][jp] = 0ull;

    const int arow = tid >> 1, acol = (tid & 1) * 4;
    const int brow = tid >> 5, bcol = (tid & 31) * 4;
    const float* Ap = A + (size_t)(m0 + arow) * K + acol;
    const float* Wp = W + (size_t)brow * N + n0 + bcol;

    {
        float4 av = *(const float4*)(Ap);
        float4 bv = *(const float4*)(Wp);
        As[0][acol + 0][arow] = av.x;
        As[0][acol + 1][arow] = av.y;
        As[0][acol + 2][arow] = av.z;
        As[0][acol + 3][arow] = av.w;
        *(float4*)&Bs[0][brow][bcol] = bv;
    }
    __syncthreads();

    int buf = 0;
    for (int k0 = 0; k0 < K; k0 += 8) {
        float4 av, bv;
        const bool has_next = (k0 + 8) < K;
        if (has_next) {
            av = *(const float4*)(Ap + k0 + 8);
            bv = *(const float4*)(Wp + (size_t)(k0 + 8) * N);
        }
#pragma unroll
        for (int kk = 0; kk < 8; ++kk) {
            float4 a0 = *(const float4*)&As[buf][kk][ty * 8];
            float4 a1 = *(const float4*)&As[buf][kk][ty * 8 + 4];
            ulonglong2 b01 = *(const ulonglong2*)&Bs[buf][kk][tx * 8];
            ulonglong2 b23 = *(const ulonglong2*)&Bs[buf][kk][tx * 8 + 4];
            unsigned long long b2[4] = {b01.x, b01.y, b23.x, b23.y};
            float ar[8] = {a0.x, a0.y, a0.z, a0.w, a1.x, a1.y, a1.z, a1.w};
#pragma unroll
            for (int i = 0; i < 8; ++i) {
                unsigned long long pa = pack2(ar[i]);
#pragma unroll
                for (int jp = 0; jp < 4; ++jp) FFMA2(acc2[i][jp], pa, b2[jp]);
            }
        }
        if (has_next) {
            const int nb = buf ^ 1;
            As[nb][acol + 0][arow] = av.x;
            As[nb][acol + 1][arow] = av.y;
            As[nb][acol + 2][arow] = av.z;
            As[nb][acol + 3][arow] = av.w;
            *(float4*)&Bs[nb][brow][bcol] = bv;
            __syncthreads();
            buf = nb;
        }
    }

#pragma unroll
    for (int i = 0; i < 8; ++i) {
        int r = m0 + ty * 8 + i;
        float accf[8];
#pragma unroll
        for (int jp = 0; jp < 4; ++jp) unpack2(acc2[i][jp], accf[2 * jp], accf[2 * jp + 1]);
#pragma unroll
        for (int j = 0; j < 8; ++j) {
            int c = n0 + tx * 8 + j;
            float v = accf[j] + bias[c];
            int bb = r / T, tl = r - bb * T;
            int h = c >> 6, d = c & 63;
            g_K[((size_t)((bb * Hn + h) * T + tl) << 6) + d] = v;
        }
    }
}

// ---------------------------------------------------------------------------
// bf16x2 split of ctx activations: A -> 2 bf16 planes in g_Asp (stride MK).
// ---------------------------------------------------------------------------
__global__ void split_A_k(const float* __restrict__ A, size_t MK)
{
    for (size_t i = ((size_t)blockIdx.x * 256 + threadIdx.x) * 2; i < MK;
         i += (size_t)gridDim.x * 512) {
        float2 f = *(const float2*)(A + i);
        __nv_bfloat16 ax1 = __float2bfloat16(f.x);
        __nv_bfloat16 ax2 = __float2bfloat16(f.x - __bfloat162float(ax1));
        __nv_bfloat16 ay1 = __float2bfloat16(f.y);
        __nv_bfloat16 ay2 = __float2bfloat16(f.y - __bfloat162float(ay1));
        *(__nv_bfloat162*)(g_Asp + i)      = __nv_bfloat162(ax1, ay1);
        *(__nv_bfloat162*)(g_Asp + MK + i) = __nv_bfloat162(ax2, ay2);
    }
}

// ---------------------------------------------------------------------------
// W split + transpose: W[K][1024] f32 -> g_Ws[WIDX] 2 bf16 planes [1024][K].
// ---------------------------------------------------------------------------
template <int WIDX>
__global__ void split_W_k(const float* __restrict__ W, int K)
{
    __shared__ float t[32][33];
    const int k0 = blockIdx.y * 32, n0 = blockIdx.x * 32;
    const int tx = threadIdx.x, ty = threadIdx.y;   // (32, 8)
#pragma unroll
    for (int i = 0; i < 4; ++i)
        t[ty + 8 * i][tx] = W[(size_t)(k0 + ty + 8 * i) * 1024 + n0 + tx];
    __syncthreads();
    __nv_bfloat16* P = g_Ws[WIDX];
    const size_t NK = (size_t)1024 * K;
#pragma unroll
    for (int i = 0; i < 4; ++i) {
        int n = ty + 8 * i;
        float f = t[tx][n];                          // = W[k0+tx][n0+n]
        __nv_bfloat16 b1 = __float2bfloat16(f);
        __nv_bfloat16 b2 = __float2bfloat16(f - __bfloat162float(b1));
        size_t o = (size_t)(n0 + n) * K + k0 + tx;
        P[o] = b1; P[NK + o] = b2;
    }
}

// ---------------------------------------------------------------------------
// wmma bf16x2 GEMM: C[M,1024] = A @ W + bias via 3 split products
// (A1B1 + A1B2 + A2B1) folded into one extended-K loop. Tile 128m x 64n x 32k,
// 8 warps (4m x 2n), HMMA m16n16k16 bf16->f32, double-buffered smem.
// DST 2: head-scatter to g_V; DST 4: plain out.
// ---------------------------------------------------------------------------
template <int DST>
__global__ __launch_bounds__(256, 2) void wmma_gemm(
    const float* __restrict__ bias, float* __restrict__ Cext, int M, int K, int T)
{
    __shared__ __align__(16) unsigned char smraw[30720];
    __shared__ float sbias[64];

    const int tid = threadIdx.x, wid = tid >> 5;
    const int wm = wid & 3, wn = wid >> 2;
    const int n0 = blockIdx.x * 64, m0 = blockIdx.y * 128;

    auto Arow = [&](int buf, int r) -> __nv_bfloat16* {
        return (__nv_bfloat16*)(smraw + buf * 10240 + r * 80);
    };
    auto Brow = [&](int buf, int r) -> __nv_bfloat16* {
        return (__nv_bfloat16*)(smraw + 20480 + buf * 5120 + r * 80);
    };

    if (tid < 64) sbias[tid] = bias[n0 + tid];

    const int WIDX = (DST == 2) ? 0 : 1;
    const __nv_bfloat16* Wt = g_Ws[WIDX];
    const size_t MK = (size_t)M * K, NK = (size_t)1024 * K;
    const int kch = K >> 5, nch = 3 * kch;
    const int PA[3] = {0, 0, 1};
    const int PB[3] = {0, 1, 0};

    wmma::fragment<wmma::accumulator, 16, 16, 16, float> acc[2][2];
#pragma unroll
    for (int i = 0; i < 2; ++i)
#pragma unroll
        for (int j = 0; j < 2; ++j) wmma::fill_fragment(acc[i][j], 0.f);

    {
        const __nv_bfloat16* gA = g_Asp + (size_t)m0 * K;
        const __nv_bfloat16* gB = Wt + (size_t)n0 * K;
#pragma unroll
        for (int u = 0; u < 2; ++u) {
            int idx = u * 256 + tid, row = idx >> 2, c8 = idx & 3;
            uint4 v = *(const uint4*)(gA + (size_t)row * K + c8 * 8);
            *(uint4*)(Arow(0, row) + c8 * 8) = v;
        }
        {
            int row = tid >> 2, c8 = tid & 3;
            uint4 v = *(const uint4*)(gB + (size_t)row * K + c8 * 8);
            *(uint4*)(Brow(0, row) + c8 * 8) = v;
        }
    }
    __syncthreads();

    int buf = 0;
    for (int c = 0; c < nch; ++c) {
        uint4 va0, va1, vb;
        const bool has_next = (c + 1) < nch;
        if (has_next) {
            const int cn = c + 1, sub = cn / kch, ko = (cn - sub * kch) << 5;
            const __nv_bfloat16* gA = g_Asp + (size_t)PA[sub] * MK + (size_t)m0 * K + ko;
            const __nv_bfloat16* gB = Wt + (size_t)PB[sub] * NK + (size_t)n0 * K + ko;
            {
                int i0 = tid, r = i0 >> 2, c8 = i0 & 3;
                va0 = *(const uint4*)(gA + (size_t)r * K + c8 * 8);
            }
            {
                int i1 = 256 + tid, r = i1 >> 2, c8 = i1 & 3;
                va1 = *(const uint4*)(gA + (size_t)r * K + c8 * 8);
            }
            {
                int r = tid >> 2, c8 = tid & 3;
                vb = *(const uint4*)(gB + (size_t)r * K + c8 * 8);
            }
        }

#pragma unroll
        for (int ks = 0; ks < 2; ++ks) {
            wmma::fragment<wmma::matrix_a, 16, 16, 16, __nv_bfloat16, wmma::row_major> af[2];
            wmma::fragment<wmma::matrix_b, 16, 16, 16, __nv_bfloat16, wmma::col_major> bf[2];
#pragma unroll
            for (int mi = 0; mi < 2; ++mi)
                wmma::load_matrix_sync(af[mi], Arow(buf, wm * 32 + mi * 16) + ks * 16, 40);
#pragma unroll
            for (int ni = 0; ni < 2; ++ni)
                wmma::load_matrix_sync(bf[ni], Brow(buf, wn * 32 + ni * 16) + ks * 16, 40);
#pragma unroll
            for (int mi = 0; mi < 2; ++mi)
#pragma unroll
                for (int ni = 0; ni < 2; ++ni)
                    wmma::mma_sync(acc[mi][ni], af[mi], bf[ni], acc[mi][ni]);
        }

        if (has_next) {
            const int nb = buf ^ 1;
            {
                int i0 = tid, r = i0 >> 2, c8 = i0 & 3;
                *(uint4*)(Arow(nb, r) + c8 * 8) = va0;
            }
            {
                int i1 = 256 + tid, r = i1 >> 2, c8 = i1 & 3;
                *(uint4*)(Arow(nb, r) + c8 * 8) = va1;
            }
            {
                int r = tid >> 2, c8 = tid & 3;
                *(uint4*)(Brow(nb, r) + c8 * 8) = vb;
            }
            __syncthreads();
            buf = nb;
        }
    }

    float (*Cs)[36] = (float (*)[36])smraw;
    const int r = tid >> 1, hc = (tid & 1) * 16;
    const int m = m0 + r;
    float* dst;
    if (DST == 2) {
        int bb = m / T, tl = m - bb * T, h = n0 >> 6;
        dst = g_V + ((size_t)((bb * Hn + h) * T + tl) << 6);
    } else {
        dst = Cext + (size_t)m * 1024 + n0;
    }

#pragma unroll
    for (int p = 0; p < 2; ++p) {
        __syncthreads();
        if (wn == p) {
#pragma unroll
            for (int mi = 0; mi < 2; ++mi)
#pragma unroll
                for (int ni = 0; ni < 2; ++ni)
                    wmma::store_matrix_sync(&Cs[wm * 32 + mi * 16][ni * 16],
                                            acc[mi][ni], 36, wmma::mem_row_major);
        }
        __syncthreads();
#pragma unroll
        for (int j4 = 0; j4 < 4; ++j4) {
            int cc = hc + j4 * 4;
            float4 v;
            v.x = Cs[r][cc + 0] + sbias[p * 32 + cc + 0];
            v.y = Cs[r][cc + 1] + sbias[p * 32 + cc + 1];
            v.z = Cs[r][cc + 2] + sbias[p * 32 + cc + 2];
            v.w = Cs[r][cc + 3] + sbias[p * 32 + cc + 3];
            *(float4*)(dst + p * 32 + cc) = v;
        }
    }
}

// ---------------------------------------------------------------------------
// QK^T logits GEMM (bitwise-identical to rounds 4-14)
// ---------------------------------------------------------------------------
__global__ __launch_bounds__(256, 2) void qk_logits_k(const void* __restrict__ mask)
{
    extern __shared__ float sm[];
    float (*Qs)[132] = (float (*)[132])sm;
    float (*Ks)[132] = (float (*)[132])(sm + 64 * 132);

    const int tid = threadIdx.x;
    const int bh = blockIdx.z;
    const int q0 = blockIdx.y * 128, n0 = blockIdx.x * 128;
    const float* Qb = g_Q + ((size_t)bh * TQn + q0) * 64;
    const float* Kb = g_K + ((size_t)bh * TKn + n0) * 64;

    {
        const int m = tid & 127, half = tid >> 7;
#pragma unroll
        for (int cc = 0; cc < 8; ++cc) {
            const int d4 = half + 2 * cc;
            float4 qv = *(const float4*)(Qb + (size_t)m * 64 + d4 * 4);
            Qs[d4 * 4 + 0][m] = qv.x * 0.125f;
            Qs[d4 * 4 + 1][m] = qv.y * 0.125f;
            Qs[d4 * 4 + 2][m] = qv.z * 0.125f;
            Qs[d4 * 4 + 3][m] = qv.w * 0.125f;
            float4 kv = *(const float4*)(Kb + (size_t)m * 64 + d4 * 4);
            Ks[d4 * 4 + 0][m] = kv.x;
            Ks[d4 * 4 + 1][m] = kv.y;
            Ks[d4 * 4 + 2][m] = kv.z;
            Ks[d4 * 4 + 3][m] = kv.w;
        }
    }
    __syncthreads();

    const int tx = tid & 15, ty = tid >> 4;
    unsigned long long acc2[8][4];
#pragma unroll
    for (int i = 0; i < 8; ++i)
#pragma unroll
        for (int jp = 0; jp < 4; ++jp) acc2[i][jp] = 0ull;

#pragma unroll 8
    for (int kk = 0; kk < 64; ++kk) {
        float4 a0 = *(const float4*)&Qs[kk][ty * 8];
        float4 a1 = *(const float4*)&Qs[kk][ty * 8 + 4];
        ulonglong2 b01 = *(const ulonglong2*)&Ks[kk][tx * 8];
        ulonglong2 b23 = *(const ulonglong2*)&Ks[kk][tx * 8 + 4];
        unsigned long long b2[4] = {b01.x, b01.y, b23.x, b23.y};
        float ar[8] = {a0.x, a0.y, a0.z, a0.w, a1.x, a1.y, a1.z, a1.w};
#pragma unroll
        for (int i = 0; i < 8; ++i) {
            unsigned long long pa = pack2(ar[i]);
#pragma unroll
            for (int jp = 0; jp < 4; ++jp) FFMA2(acc2[i][jp], pa, b2[jp]);
        }
    }

    const int mode = g_mask_mode, b = bh >> 4;
    unsigned char mku[8];
#pragma unroll
    for (int j = 0; j < 8; ++j) mku[j] = mask_at(mask, mode, b * TKn + n0 + tx * 8 + j);

#pragma unroll
    for (int i = 0; i < 8; ++i) {
        float* Lp = g_L + ((size_t)bh * TQn + q0 + ty * 8 + i) * TKn + n0 + tx * 8;
        float o[8];
#pragma unroll
        for (int jp = 0; jp < 4; ++jp) unpack2(acc2[i][jp], o[2 * jp], o[2 * jp + 1]);
#pragma unroll
        for (int j = 0; j < 8; ++j) if (mku[j]) o[j] = NEG_BIG;
        __stcs((float4*)Lp,       make_float4(o[0], o[1], o[2], o[3]));
        __stcs((float4*)(Lp + 4), make_float4(o[4], o[5], o[6], o[7]));
    }
}

// ---------------------------------------------------------------------------
// Top-64 + softmax + sparse AV (unchanged from round 11)
// ---------------------------------------------------------------------------
__device__ __forceinline__ int cnt_ge(const float (&a)[64], float t)
{
    int c = 0;
#pragma unroll
    for (int j = 0; j < 64; ++j) c += (a[j] >= t) ? 1 : 0;
    return __reduce_add_sync(0xffffffffu, c);
}

__global__ __launch_bounds__(256, 2) void topk_av_k()
{
    __shared__ int   skey[8][80];
    __shared__ float swgt[8][80];

    const int lane = threadIdx.x & 31, w = threadIdx.x >> 5;
    const int b = blockIdx.z, h = blockIdx.y;
    const int bh = b * Hn + h;
    const int q = blockIdx.x * 8 + w;

    const float* Lq = g_L + ((size_t)bh * TQn + q) * TKn;
    float acc[64];
#pragma unroll
    for (int j = 0; j < 64; ++j) acc[j] = __ldcs(Lq + j * 32 + lane);

    float m = NEG_BIG;
#pragma unroll
    for (int j = 0; j < 64; ++j) m = fmaxf(m, acc[j]);
#pragma unroll
    for (int o = 16; o > 0; o >>= 1) m = fmaxf(m, __shfl_xor_sync(0xffffffffu, m, o));

    float lo = m - 32.0f, hi = m;
    int clo = cnt_ge(acc, lo), chi = 1;
    int guard = 0;
    while (clo < 64 && guard++ < 90) { lo = m - 2.0f * (m - lo); clo = cnt_ge(acc, lo); }

    for (int it = 0; it < 32 && clo != 64; ++it) {
        float t;
        if (it == 0) {
            t = m - 1.9f;
        } else {
            float f = (__logf(64.f) - __logf((float)chi)) /
                      (__logf((float)clo) - __logf((float)chi));
            t = hi + f * (lo - hi);
        }
        if (!(t > lo && t < hi)) t = 0.5f * (lo + hi);
        if (!(t > lo && t < hi)) break;
        int c2 = cnt_ge(acc, t);
        if (c2 >= 64) { lo = t; clo = c2; } else { hi = t; chi = c2; }
    }
    const float thr = lo;

    int base = 0;
#pragma unroll
    for (int j = 0; j < 64; ++j) {
        bool sel = acc[j] >= thr;
        unsigned bal = __ballot_sync(0xffffffffu, sel);
        if (sel) {
            int pos = base + __popc(bal & ((1u << lane) - 1u));
            if (pos < 80) {
                skey[w][pos] = j * 32 + lane;
                swgt[w][pos] = __expf(acc[j] - m);
            }
        }
        base += __popc(bal);
    }
    const int nsel = base < 80 ? base : 80;
    __syncwarp();

    float z = 0.f;
    for (int i = lane; i < nsel; i += 32) z += swgt[w][i];
#pragma unroll
    for (int o = 16; o > 0; o >>= 1) z += __shfl_xor_sync(0xffffffffu, z, o);

    const float* Vb = g_V + (size_t)bh * TKn * 64;
    float o0 = 0.f, o1 = 0.f;
    int i = 0;
    for (; i + 8 <= nsel; i += 8) {
        int   kv[8]; float wv[8];
#pragma unroll
        for (int u = 0; u < 8; ++u) { kv[u] = skey[w][i + u]; wv[u] = swgt[w][i + u]; }
        float2 vv[8];
#pragma unroll
        for (int u = 0; u < 8; ++u)
            vv[u] = *(const float2*)(Vb + (size_t)kv[u] * 64 + 2 * lane);
#pragma unroll
        for (int u = 0; u < 8; ++u) { o0 += wv[u] * vv[u].x; o1 += wv[u] * vv[u].y; }
    }
    for (; i < nsel; ++i) {
        float wv = swgt[w][i];
        float2 vv = *(const float2*)(Vb + (size_t)skey[w][i] * 64 + 2 * lane);
        o0 += wv * vv.x;
        o1 += wv * vv.y;
    }

    const float inv = 1.0f / z;
    const float r0 = o0 * inv, r1 = o1 * inv;
    __nv_bfloat16 x1 = __float2bfloat16(r0);
    __nv_bfloat16 x2 = __float2bfloat16(r0 - __bfloat162float(x1));
    __nv_bfloat16 y1 = __float2bfloat16(r1);
    __nv_bfloat16 y2 = __float2bfloat16(r1 - __bfloat162float(y1));
    const size_t MK = (size_t)Bb * TQn * DQn;
    const size_t o = ((size_t)(b * TQn + q)) * DQn + h * 64 + 2 * lane;
    *(__nv_bfloat162*)(g_Asp + o)      = __nv_bfloat162(x1, y1);
    *(__nv_bfloat162*)(g_Asp + MK + o) = __nv_bfloat162(x2, y2);
}

// ---------------------------------------------------------------------------
// Launch: 3-stream graph fork/join.
//   s0: detect -> qproj -> (wait e1) -> qk -> (wait e2) -> topk -> wmmaOut
//   s1: kproj (e1)
//   s2: splitW0 -> splitW1 -> splitA -> wmmaV (e2)
// Streams/events created once on first (uncaptured) call; non-blocking
// streams avoid legacy-stream implicit sync during capture.
// ---------------------------------------------------------------------------
extern "C" void kernel_launch(void* const* d_in, const int* in_sizes, int n_in,
                              void* d_out, int out_size)
{
    const float* x   = (const float*)d_in[0];
    const float* ctx = (const float*)d_in[1];
    const void*  msk = d_in[2];
    const float* Wq = (const float*)d_in[3];
    const float* bq = (const float*)d_in[4];
    const float* Wk = (const float*)d_in[5];
    const float* bk = (const float*)d_in[6];
    const float* Wv = (const float*)d_in[7];
    const float* bv = (const float*)d_in[8];
    const float* Wo = (const float*)d_in[9];
    const float* bo = (const float*)d_in[10];
    float* out = (float*)d_out;

    const int qk_smem = 2 * 64 * 132 * sizeof(float);   // 67.6 KB

    static cudaStream_t s1 = nullptr, s2 = nullptr;
    static cudaEvent_t eF = nullptr, e1 = nullptr, e2 = nullptr;
    if (!s1) {
        cudaFuncSetAttribute(qk_logits_k, cudaFuncAttributeMaxDynamicSharedMemorySize, qk_smem);
        cudaStreamCreateWithFlags(&s1, cudaStreamNonBlocking);
        cudaStreamCreateWithFlags(&s2, cudaStreamNonBlocking);
        cudaEventCreateWithFlags(&eF, cudaEventDisableTiming);
        cudaEventCreateWithFlags(&e1, cudaEventDisableTiming);
        cudaEventCreateWithFlags(&e2, cudaEventDisableTiming);
    }

    // s0 head
    detect_mask_kernel<<<1, 256>>>((const unsigned char*)msk);

    // fork
    cudaEventRecord(eF, 0);
    cudaStreamWaitEvent(s1, eF, 0);
    cudaStreamWaitEvent(s2, eF, 0);

    // s0: Q projection
    qproj_k<<<dim3(16, 16), 256>>>(x, Wq, bq);
    // s1: K projection
    kproj_k<<<dim3(8, 32), 256, 0, s1>>>(ctx, Wk, bk);
    cudaEventRecord(e1, s1);
    // s2: V path (weight splits, ctx split, wmma V projection)
    split_W_k<0><<<dim3(32, 24), dim3(32, 8), 0, s2>>>(Wv, 768);
    split_W_k<1><<<dim3(32, 32), dim3(32, 8), 0, s2>>>(Wo, 1024);
    split_A_k<<<4096, 256, 0, s2>>>(ctx, (size_t)4096 * 768);
    wmma_gemm<2><<<dim3(16, 32), 256, 0, s2>>>(bv, nullptr, 4096, 768, 2048);
    cudaEventRecord(e2, s2);

    // s0: logits after Q (program order) and K (e1)
    cudaStreamWaitEvent(0, e1, 0);
    qk_logits_k<<<dim3(TKn / 128, TQn / 128, Bb * Hn), 256, qk_smem>>>(msk);

    // s0: topk after logits (program order) and V + g_Asp free (e2)
    cudaStreamWaitEvent(0, e2, 0);
    topk_av_k<<<dim3(TQn / 8, Hn, Bb), 256>>>();

    // s0: output projection (AO planes from topk, Wo planes from s2 via e2)
    wmma_gemm<4><<<dim3(16, 16), 256>>>(bo, out, 2048, 1024, 1024);
}